// round 13
// baseline (speedup 1.0000x reference)
#include <cuda_runtime.h>
#include <cuda_bf16.h>
#include <cuda_fp16.h>
#include <math.h>
#include <stdint.h>

#define BB 2
#define TT 2048
#define LL 6
#define HH 12
#define DD 768
#define HDIM 64
#define VV 32000
#define MM (BB*TT)          // 4096 tokens

// ---------------------------------------------------------------------------
// Scratch (device globals; no allocation allowed)
// ---------------------------------------------------------------------------
__device__ float g_x  [MM * DD];            // residual stream (fp32)
__device__ __nv_bfloat16 g_h_hi[MM * DD],      g_h_lo[MM * DD];       // LN out split
__device__ __nv_bfloat16 g_y_hi[MM * DD],      g_y_lo[MM * DD];       // attn out split
__device__ __nv_bfloat16 g_ff_hi[MM * 4 * DD], g_ff_lo[MM * 4 * DD];  // gelu out split
// qkv split outputs (written by QKV GEMM epilogue)
__device__ __nv_bfloat16 g_q_hi[MM * DD],  g_q_lo[MM * DD];   // [tok][768]
__device__ __nv_bfloat16 g_k_hi[MM * DD],  g_k_lo[MM * DD];   // [tok][768]
__device__ __nv_bfloat16 g_vt_hi[MM * DD], g_vt_lo[MM * DD];  // [b,h][hd][tok]
// fp16 path for lm_head
__device__ __half g_h16_hi[MM * DD], g_h16_lo[MM * DD];
__device__ __half g_emb16[VV * DD];                            // [V][D] fp16
// transposed + split weights [N,K]
__device__ __nv_bfloat16 g_qkvT_hi[LL * 3 * DD * DD], g_qkvT_lo[LL * 3 * DD * DD];
__device__ __nv_bfloat16 g_outT_hi[LL * DD * DD],     g_outT_lo[LL * DD * DD];
__device__ __nv_bfloat16 g_ff1T_hi[LL * 4 * DD * DD], g_ff1T_lo[LL * 4 * DD * DD];
__device__ __nv_bfloat16 g_ff2T_hi[LL * 4 * DD * DD], g_ff2T_lo[LL * 4 * DD * DD];

// ---------------------------------------------------------------------------
// PTX helpers
// ---------------------------------------------------------------------------
__device__ __forceinline__ uint32_t smem_u32(const void* p) {
    uint32_t a;
    asm("{ .reg .u64 t; cvta.to.shared.u64 t, %1; cvt.u32.u64 %0, t; }"
        : "=r"(a) : "l"(p));
    return a;
}

__device__ __forceinline__ void cpa16(uint32_t dst, const void* src) {
    asm volatile("cp.async.cg.shared.global [%0], [%1], 16;" :: "r"(dst), "l"(src));
}
#define CPA_COMMIT() asm volatile("cp.async.commit_group;" ::: "memory")

__device__ __forceinline__ void ldsm4(uint32_t* r, uint32_t addr) {
    asm volatile("ldmatrix.sync.aligned.m8n8.x4.shared.b16 {%0,%1,%2,%3}, [%4];"
        : "=r"(r[0]), "=r"(r[1]), "=r"(r[2]), "=r"(r[3]) : "r"(addr));
}

__device__ __forceinline__ void mma_bf16(float* d, const uint32_t* a, const uint32_t* b) {
    asm volatile(
        "mma.sync.aligned.m16n8k16.row.col.f32.bf16.bf16.f32 "
        "{%0,%1,%2,%3}, {%4,%5,%6,%7}, {%8,%9}, {%0,%1,%2,%3};"
        : "+f"(d[0]), "+f"(d[1]), "+f"(d[2]), "+f"(d[3])
        : "r"(a[0]), "r"(a[1]), "r"(a[2]), "r"(a[3]), "r"(b[0]), "r"(b[1]));
}
__device__ __forceinline__ void mma_fp16(float* d, const uint32_t* a, const uint32_t* b) {
    asm volatile(
        "mma.sync.aligned.m16n8k16.row.col.f32.f16.f16.f32 "
        "{%0,%1,%2,%3}, {%4,%5,%6,%7}, {%8,%9}, {%0,%1,%2,%3};"
        : "+f"(d[0]), "+f"(d[1]), "+f"(d[2]), "+f"(d[3])
        : "r"(a[0]), "r"(a[1]), "r"(a[2]), "r"(a[3]), "r"(b[0]), "r"(b[1]));
}

__device__ __forceinline__ void split_bf(float v, __nv_bfloat16& hi, __nv_bfloat16& lo) {
    hi = __float2bfloat16(v);
    lo = __float2bfloat16(v - __bfloat162float(hi));
}
__device__ __forceinline__ uint32_t pack_bf2(float x, float y) {
    __nv_bfloat16 a = __float2bfloat16(x), b = __float2bfloat16(y);
    uint16_t ua = *(uint16_t*)&a, ub = *(uint16_t*)&b;
    return (uint32_t)ua | ((uint32_t)ub << 16);
}
__device__ __forceinline__ float bf_round(float x) {
    __nv_bfloat16 h = __float2bfloat16(x);
    return __bfloat162float(h);
}
__device__ __forceinline__ float gelu_exact(float v) {
    return 0.5f * v * (1.0f + erff(v * 0.70710678118654752f));
}

// ---------------------------------------------------------------------------
// Weight prep: transpose+split W[K,N] -> Thi/Tlo [N,K], batched over layers
// ---------------------------------------------------------------------------
__global__ __launch_bounds__(256) void wprep_T(
    const float* __restrict__ W, __nv_bfloat16* __restrict__ Thi,
    __nv_bfloat16* __restrict__ Tlo, int K, int N)
{
    __shared__ float tile[32][33];
    size_t lw = (size_t)blockIdx.z * K * N;
    const float* Wl = W + lw;
    __nv_bfloat16* Thl = Thi + lw;
    __nv_bfloat16* Tll = Tlo + lw;
    int n0 = blockIdx.x * 32, k0 = blockIdx.y * 32;
    int tx = threadIdx.x & 31, ty = threadIdx.x >> 5;
    #pragma unroll
    for (int i = ty; i < 32; i += 8)
        tile[i][tx] = Wl[(size_t)(k0 + i) * N + n0 + tx];
    __syncthreads();
    #pragma unroll
    for (int i = ty; i < 32; i += 8) {
        float v = tile[tx][i];
        size_t o = (size_t)(n0 + i) * K + k0 + tx;
        __nv_bfloat16 h, l; split_bf(v, h, l);
        Thl[o] = h; Tll[o] = l;
    }
}

// tok_emb -> fp16 (single rounding), for lm_head B operand
__global__ __launch_bounds__(256) void wprep_S16(
    const float4* __restrict__ W, __half* __restrict__ out, int n4)
{
    for (int i = blockIdx.x * blockDim.x + threadIdx.x; i < n4;
         i += gridDim.x * blockDim.x) {
        float4 v = W[i];
        ((__half2*)out)[i * 2    ] = __floats2half2_rn(v.x, v.y);
        ((__half2*)out)[i * 2 + 1] = __floats2half2_rn(v.z, v.w);
    }
}

// ---------------------------------------------------------------------------
// Embedding
// ---------------------------------------------------------------------------
__global__ __launch_bounds__(256) void embed_kernel(
    const int* __restrict__ idx, const float* __restrict__ tok_emb,
    const float* __restrict__ pos_emb, float* __restrict__ x)
{
    int tok = blockIdx.x;
    int id  = idx[tok];
    int p   = tok % TT;
    const float* te = tok_emb + (size_t)id * DD;
    const float* pe = pos_emb + (size_t)p  * DD;
    float* xr = x + (size_t)tok * DD;
    for (int d = threadIdx.x; d < DD; d += 256)
        xr[d] = te[d] + pe[d];
}

// ---------------------------------------------------------------------------
// LayerNorm -> split outputs. F16=0: bf16 hi/lo; F16=1: fp16 hi/lo.
// ---------------------------------------------------------------------------
template<int F16>
__global__ __launch_bounds__(256) void ln_kernel(
    const float* __restrict__ x, const float* __restrict__ w,
    const float* __restrict__ b, void* __restrict__ ohi_v,
    void* __restrict__ olo_v)
{
    int tok = blockIdx.x;
    int t   = threadIdx.x;
    const float* xr = x + (size_t)tok * DD;
    float v0 = xr[t], v1 = xr[t + 256], v2 = xr[t + 512];
    float s  = v0 + v1 + v2;
    float s2 = v0*v0 + v1*v1 + v2*v2;
    #pragma unroll
    for (int off = 16; off; off >>= 1) {
        s  += __shfl_down_sync(0xffffffffu, s,  off);
        s2 += __shfl_down_sync(0xffffffffu, s2, off);
    }
    __shared__ float red[16];
    __shared__ float mean_s, rstd_s;
    int wid = t >> 5, lid = t & 31;
    if (lid == 0) { red[wid] = s; red[8 + wid] = s2; }
    __syncthreads();
    if (t == 0) {
        float S = 0.f, S2 = 0.f;
        #pragma unroll
        for (int i = 0; i < 8; i++) { S += red[i]; S2 += red[8 + i]; }
        float mean = S * (1.0f / DD);
        float var  = S2 * (1.0f / DD) - mean * mean;
        mean_s = mean;
        rstd_s = rsqrtf(var + 1e-5f);
    }
    __syncthreads();
    float mean = mean_s, rstd = rstd_s;
    size_t base = (size_t)tok * DD;
    #pragma unroll
    for (int q = 0; q < 3; q++) {
        int d = t + q * 256;
        float v = (q == 0 ? v0 : (q == 1 ? v1 : v2));
        float o = (v - mean) * rstd * w[d] + b[d];
        if (F16) {
            __half h = __float2half(o);
            __half l = __float2half(o - __half2float(h));
            ((__half*)ohi_v)[base + d] = h;
            ((__half*)olo_v)[base + d] = l;
        } else {
            __nv_bfloat16 h, l; split_bf(o, h, l);
            ((__nv_bfloat16*)ohi_v)[base + d] = h;
            ((__nv_bfloat16*)olo_v)[base + d] = l;
        }
    }
}

// ---------------------------------------------------------------------------
// Flash attention on HMMA, Q-tile = 128 rows (256 threads, 8 warps x 16 rows).
// K/V tiles 64 rows, double-buffered. 2 CTAs/SM. (R11 verified)
// ---------------------------------------------------------------------------
#define FP2 144
#define FMQ (128 * FP2)            // Q mat: 18432
#define FMK (64 * FP2)             // K/V mat: 9216
#define FLASH3_SMEM (2 * FMQ + 8 * FMK)   // 110592

__global__ __launch_bounds__(256, 2) void flash_hmma3(
    const __nv_bfloat16* __restrict__ q_hi, const __nv_bfloat16* __restrict__ q_lo,
    const __nv_bfloat16* __restrict__ k_hi, const __nv_bfloat16* __restrict__ k_lo,
    const __nv_bfloat16* __restrict__ vt_hi, const __nv_bfloat16* __restrict__ vt_lo,
    __nv_bfloat16* __restrict__ y_hi, __nv_bfloat16* __restrict__ y_lo)
{
    extern __shared__ char fsm[];
    const uint32_t sb  = smem_u32(fsm);
    const uint32_t sQh = sb, sQl = sb + FMQ;
    const uint32_t sKV = sb + 2 * FMQ;

    const int qt = blockIdx.x, hh = blockIdx.y, b = blockIdx.z;
    const int t = threadIdx.x, lane = t & 31, w = t >> 5;
    const unsigned FULL = 0xffffffffu;
    const int NKT = 2 * qt + 2;    // k-tiles for this q-tile

    // ---- Q prologue ----
    {
        const __nv_bfloat16* srcs[2] = {q_hi, q_lo};
        #pragma unroll
        for (int m2 = 0; m2 < 2; m2++) {
            #pragma unroll
            for (int j = 0; j < 4; j++) {
                int id = t * 4 + j;
                int r = id >> 3, c = id & 7;
                int tok = b * TT + qt * 128 + r;
                cpa16(sb + m2 * FMQ + r * FP2 + c * 16,
                      srcs[m2] + (size_t)tok * DD + hh * HDIM + c * 8);
            }
        }
        CPA_COMMIT();
    }
    auto load_kv = [&](int s, int kt) {
        const uint32_t base = sKV + s * (4 * FMK);
        #pragma unroll
        for (int j = 0; j < 2; j++) {
            int id = t * 2 + j;
            int r = id >> 3, c = id & 7;
            int tok = b * TT + kt * 64 + r;
            size_t koff = (size_t)tok * DD + hh * HDIM + c * 8;
            cpa16(base + 0 * FMK + r * FP2 + c * 16, k_hi + koff);
            cpa16(base + 1 * FMK + r * FP2 + c * 16, k_lo + koff);
            size_t voff = ((size_t)(b * HH + hh) * HDIM + r) * TT + kt * 64 + c * 8;
            cpa16(base + 2 * FMK + r * FP2 + c * 16, vt_hi + voff);
            cpa16(base + 3 * FMK + r * FP2 + c * 16, vt_lo + voff);
        }
        CPA_COMMIT();
    };

    float m[2] = {-1e30f, -1e30f}, l[2] = {0.f, 0.f};
    float O[8][4];
    #pragma unroll
    for (int nt = 0; nt < 8; nt++)
        #pragma unroll
        for (int e = 0; e < 4; e++) O[nt][e] = 0.f;

    const uint32_t aOff = (uint32_t)((w * 16 + (lane & 15)) * FP2 + (lane >> 4) * 16);
    const uint32_t bOff = (uint32_t)(((lane & 7) + (lane >> 4) * 8) * FP2
                                     + ((lane >> 3) & 1) * 16);

    load_kv(0, 0);

    for (int kt = 0; kt < NKT; kt++) {
        asm volatile("cp.async.wait_group 0;" ::: "memory");
        __syncthreads();
        if (kt + 1 < NKT) load_kv((kt + 1) & 1, kt + 1);

        const uint32_t bK = sKV + (kt & 1) * (4 * FMK);

        float S[8][4];
        #pragma unroll
        for (int nt = 0; nt < 8; nt++)
            #pragma unroll
            for (int e = 0; e < 4; e++) S[nt][e] = 0.f;

        #pragma unroll
        for (int kk = 0; kk < 4; kk++) {
            uint32_t qh[4], ql[4];
            ldsm4(qh, sQh + aOff + kk * 32);
            ldsm4(ql, sQl + aOff + kk * 32);
            #pragma unroll
            for (int np = 0; np < 4; np++) {
                uint32_t kh[4], kl[4];
                ldsm4(kh, bK + 0 * FMK + bOff + np * (16 * FP2) + kk * 32);
                ldsm4(kl, bK + 1 * FMK + bOff + np * (16 * FP2) + kk * 32);
                #pragma unroll
                for (int sub = 0; sub < 2; sub++)
                    mma_bf16(S[2 * np + sub], qh, &kh[sub * 2]);
                #pragma unroll
                for (int sub = 0; sub < 2; sub++)
                    mma_bf16(S[2 * np + sub], qh, &kl[sub * 2]);
                #pragma unroll
                for (int sub = 0; sub < 2; sub++)
                    mma_bf16(S[2 * np + sub], ql, &kh[sub * 2]);
            }
        }

        if (kt >= 2 * qt) {
            #pragma unroll
            for (int nt = 0; nt < 8; nt++)
                #pragma unroll
                for (int e = 0; e < 4; e++) {
                    int col = kt * 64 + nt * 8 + (lane & 3) * 2 + (e & 1);
                    int row = qt * 128 + w * 16 + (lane >> 2) + (e >> 1) * 8;
                    S[nt][e] = (col > row) ? -1e30f : S[nt][e] * 0.125f;
                }
        } else {
            #pragma unroll
            for (int nt = 0; nt < 8; nt++)
                #pragma unroll
                for (int e = 0; e < 4; e++) S[nt][e] *= 0.125f;
        }

        float a[2];
        #pragma unroll
        for (int h = 0; h < 2; h++) {
            float mx = -1e30f;
            #pragma unroll
            for (int nt = 0; nt < 8; nt++)
                mx = fmaxf(mx, fmaxf(S[nt][2 * h], S[nt][2 * h + 1]));
            mx = fmaxf(mx, __shfl_xor_sync(FULL, mx, 1));
            mx = fmaxf(mx, __shfl_xor_sync(FULL, mx, 2));
            float mn = fmaxf(m[h], mx);
            a[h] = __expf(m[h] - mn);
            float sum = 0.f;
            #pragma unroll
            for (int nt = 0; nt < 8; nt++) {
                float p0 = __expf(S[nt][2 * h    ] - mn);
                float p1 = __expf(S[nt][2 * h + 1] - mn);
                S[nt][2 * h] = p0; S[nt][2 * h + 1] = p1;
                sum += p0 + p1;
            }
            sum += __shfl_xor_sync(FULL, sum, 1);
            sum += __shfl_xor_sync(FULL, sum, 2);
            l[h] = l[h] * a[h] + sum;
            m[h] = mn;
        }
        #pragma unroll
        for (int nt = 0; nt < 8; nt++) {
            O[nt][0] *= a[0]; O[nt][1] *= a[0];
            O[nt][2] *= a[1]; O[nt][3] *= a[1];
        }

        #pragma unroll
        for (int kb = 0; kb < 4; kb++) {
            uint32_t pah[4], pal[4];
            {
                float x0 = S[2*kb][0], x1 = S[2*kb][1], x2 = S[2*kb][2], x3 = S[2*kb][3];
                float y0 = S[2*kb+1][0], y1 = S[2*kb+1][1], y2 = S[2*kb+1][2], y3 = S[2*kb+1][3];
                float hx0 = bf_round(x0), hx1 = bf_round(x1), hx2 = bf_round(x2), hx3 = bf_round(x3);
                float hy0 = bf_round(y0), hy1 = bf_round(y1), hy2 = bf_round(y2), hy3 = bf_round(y3);
                pah[0] = pack_bf2(hx0, hx1); pah[1] = pack_bf2(hx2, hx3);
                pah[2] = pack_bf2(hy0, hy1); pah[3] = pack_bf2(hy2, hy3);
                pal[0] = pack_bf2(x0 - hx0, x1 - hx1); pal[1] = pack_bf2(x2 - hx2, x3 - hx3);
                pal[2] = pack_bf2(y0 - hy0, y1 - hy1); pal[3] = pack_bf2(y2 - hy2, y3 - hy3);
            }
            #pragma unroll
            for (int np = 0; np < 4; np++) {
                uint32_t vh[4], vl[4];
                ldsm4(vh, bK + 2 * FMK + bOff + np * (16 * FP2) + kb * 32);
                ldsm4(vl, bK + 3 * FMK + bOff + np * (16 * FP2) + kb * 32);
                #pragma unroll
                for (int sub = 0; sub < 2; sub++)
                    mma_bf16(O[2 * np + sub], pah, &vh[sub * 2]);
                #pragma unroll
                for (int sub = 0; sub < 2; sub++)
                    mma_bf16(O[2 * np + sub], pah, &vl[sub * 2]);
                #pragma unroll
                for (int sub = 0; sub < 2; sub++)
                    mma_bf16(O[2 * np + sub], pal, &vh[sub * 2]);
            }
        }
    }

    float inv[2] = {1.0f / l[0], 1.0f / l[1]};
    #pragma unroll
    for (int nt = 0; nt < 8; nt++) {
        int col = nt * 8 + (lane & 3) * 2;
        #pragma unroll
        for (int h = 0; h < 2; h++) {
            int row = qt * 128 + w * 16 + (lane >> 2) + h * 8;
            int tok = b * TT + row;
            size_t base = (size_t)tok * DD + hh * HDIM + col;
            float v0 = O[nt][2 * h    ] * inv[h];
            float v1 = O[nt][2 * h + 1] * inv[h];
            float h0 = bf_round(v0), h1 = bf_round(v1);
            *(uint32_t*)((char*)y_hi + base * 2) = pack_bf2(h0, h1);
            *(uint32_t*)((char*)y_lo + base * 2) = pack_bf2(v0 - h0, v1 - h1);
        }
    }
}

// ---------------------------------------------------------------------------
// HMMA GEMM 64x128 tile (bf16 3-term split) — all layer GEMMs. (R9 verified)
// 8 warps: 2 (M, 32 rows) x 4 (N, 32 cols). 2 CTAs/SM.
// EPI: 1 = residual add; 2 = gelu->split; 3 = qkv split/route.
// ---------------------------------------------------------------------------
#define GPITCH 144
#define AMAT64 (64 * GPITCH)                 // 9216
#define BMAT64 (128 * GPITCH)                // 18432
#define STG64  (2 * AMAT64 + 2 * BMAT64)     // 55296
#define GEMM64_SMEM (2 * STG64)              // 110592

template<int EPI>
__global__ __launch_bounds__(256, 1) void gemm_mma64(
    const __nv_bfloat16* __restrict__ Ahi, const __nv_bfloat16* __restrict__ Alo,
    const __nv_bfloat16* __restrict__ Bhi, const __nv_bfloat16* __restrict__ Blo,
    const float* __restrict__ R, float* __restrict__ Cf,
    __nv_bfloat16* __restrict__ Chi, __nv_bfloat16* __restrict__ Clo,
    __nv_bfloat16* __restrict__ Qh, __nv_bfloat16* __restrict__ Ql,
    __nv_bfloat16* __restrict__ Kh, __nv_bfloat16* __restrict__ Kl,
    __nv_bfloat16* __restrict__ Vth, __nv_bfloat16* __restrict__ Vtl,
    int M, int N, int K)
{
    extern __shared__ char smem[];
    const uint32_t sb = smem_u32(smem);
    const int t = threadIdx.x;

    const int bm = blockIdx.y * 64;
    const int bn = blockIdx.x * 128;
    const int NK = K >> 6;
    const int lane = t & 31;
    const int w    = t >> 5;
    const int wm   = w & 1;
    const int wn   = w >> 1;

    const int rbase = t >> 3;
    const int cc    = t & 7;
    auto load_stage = [&](int s, int kt) {
        const int koff = kt * 64 + cc * 8;
        const uint32_t stg = sb + s * STG64;
        #pragma unroll
        for (int i = 0; i < 2; i++) {
            int r = rbase + 32 * i;
            cpa16(stg + r * GPITCH + cc * 16, Ahi + (size_t)(bm + r) * K + koff);
        }
        #pragma unroll
        for (int i = 0; i < 2; i++) {
            int r = rbase + 32 * i;
            cpa16(stg + AMAT64 + r * GPITCH + cc * 16, Alo + (size_t)(bm + r) * K + koff);
        }
        #pragma unroll
        for (int i = 0; i < 4; i++) {
            int r = rbase + 32 * i;
            cpa16(stg + 2 * AMAT64 + r * GPITCH + cc * 16, Bhi + (size_t)(bn + r) * K + koff);
        }
        #pragma unroll
        for (int i = 0; i < 4; i++) {
            int r = rbase + 32 * i;
            cpa16(stg + 2 * AMAT64 + BMAT64 + r * GPITCH + cc * 16,
                  Blo + (size_t)(bn + r) * K + koff);
        }
        CPA_COMMIT();
    };

    float acc[2][4][4];
    #pragma unroll
    for (int mt = 0; mt < 2; mt++)
        #pragma unroll
        for (int nt = 0; nt < 4; nt++)
            #pragma unroll
            for (int q = 0; q < 4; q++) acc[mt][nt][q] = 0.f;

    const uint32_t aOff = (uint32_t)((wm * 32 + (lane & 15)) * GPITCH + (lane >> 4) * 16);
    const uint32_t bOff = (uint32_t)((wn * 32 + (lane & 7) + (lane >> 4) * 8) * GPITCH
                                     + ((lane >> 3) & 1) * 16);

    load_stage(0, 0);

    for (int kt = 0; kt < NK; kt++) {
        const int s = kt & 1;
        asm volatile("cp.async.wait_group 0;" ::: "memory");
        __syncthreads();
        if (kt + 1 < NK) load_stage(s ^ 1, kt + 1);

        const uint32_t stg = sb + s * STG64;
        #pragma unroll
        for (int kk = 0; kk < 4; kk++) {
            uint32_t ah[2][4], al[2][4], bh[2][4], bl[2][4];
            #pragma unroll
            for (int mt = 0; mt < 2; mt++) {
                ldsm4(ah[mt], stg + aOff + mt * (16 * GPITCH) + kk * 32);
                ldsm4(al[mt], stg + AMAT64 + aOff + mt * (16 * GPITCH) + kk * 32);
            }
            #pragma unroll
            for (int np = 0; np < 2; np++) {
                ldsm4(bh[np], stg + 2 * AMAT64 + bOff + np * (16 * GPITCH) + kk * 32);
                ldsm4(bl[np], stg + 2 * AMAT64 + BMAT64 + bOff + np * (16 * GPITCH) + kk * 32);
            }
            #pragma unroll
            for (int mt = 0; mt < 2; mt++)
                #pragma unroll
                for (int nt = 0; nt < 4; nt++)
                    mma_bf16(acc[mt][nt], ah[mt], &bh[nt >> 1][(nt & 1) * 2]);
            #pragma unroll
            for (int mt = 0; mt < 2; mt++)
                #pragma unroll
                for (int nt = 0; nt < 4; nt++)
                    mma_bf16(acc[mt][nt], ah[mt], &bl[nt >> 1][(nt & 1) * 2]);
            #pragma unroll
            for (int mt = 0; mt < 2; mt++)
                #pragma unroll
                for (int nt = 0; nt < 4; nt++)
                    mma_bf16(acc[mt][nt], al[mt], &bh[nt >> 1][(nt & 1) * 2]);
        }
    }

    #pragma unroll
    for (int mt = 0; mt < 2; mt++) {
        const int row0 = bm + wm * 32 + mt * 16 + (lane >> 2);
        #pragma unroll
        for (int nt = 0; nt < 4; nt++) {
            const int col = bn + wn * 32 + nt * 8 + (lane & 3) * 2;
            #pragma unroll
            for (int half = 0; half < 2; half++) {
                const int row = row0 + half * 8;
                const float v0 = acc[mt][nt][half * 2 + 0];
                const float v1 = acc[mt][nt][half * 2 + 1];
                const size_t off = (size_t)row * N + col;
                if (EPI == 1) {
                    float2 r = *(const float2*)(R + off);
                    float2 v; v.x = r.x + v0; v.y = r.y + v1;
                    *(float2*)(Cf + off) = v;
                } else if (EPI == 2) {
                    float g0 = gelu_exact(v0), g1 = gelu_exact(v1);
                    float h0 = bf_round(g0), h1 = bf_round(g1);
                    *(uint32_t*)((char*)Chi + off * 2) = pack_bf2(h0, h1);
                    *(uint32_t*)((char*)Clo + off * 2) = pack_bf2(g0 - h0, g1 - h1);
                } else {  // EPI == 3: qkv split + route
                    float h0 = bf_round(v0), h1 = bf_round(v1);
                    if (bn < DD) {
                        size_t o2 = ((size_t)row * DD + col) * 2;
                        *(uint32_t*)((char*)Qh + o2) = pack_bf2(h0, h1);
                        *(uint32_t*)((char*)Ql + o2) = pack_bf2(v0 - h0, v1 - h1);
                    } else if (bn < 2 * DD) {
                        size_t o2 = ((size_t)row * DD + (col - DD)) * 2;
                        *(uint32_t*)((char*)Kh + o2) = pack_bf2(h0, h1);
                        *(uint32_t*)((char*)Kl + o2) = pack_bf2(v0 - h0, v1 - h1);
                    } else {
                        int c  = col - 2 * DD;
                        int hq = c >> 6, hd = c & 63;
                        int bb2 = row >> 11, tt2 = row & 2047;
                        size_t a0 = ((size_t)(bb2 * HH + hq) * HDIM + hd) * TT + tt2;
                        __nv_bfloat16 hb0 = __float2bfloat16(h0);
                        __nv_bfloat16 hb1 = __float2bfloat16(h1);
                        __nv_bfloat16 lb0 = __float2bfloat16(v0 - h0);
                        __nv_bfloat16 lb1 = __float2bfloat16(v1 - h1);
                        Vth[a0]      = hb0; Vtl[a0]      = lb0;
                        Vth[a0 + TT] = hb1; Vtl[a0 + TT] = lb1;
                    }
                }
            }
        }
    }
}

// ---------------------------------------------------------------------------
// lm_head GEMM: fp16 2-term split, 128x128 tile, K64, 2 CTAs/SM (3 mats only).
// 8 warps: 4 (M, 32 rows) x 2 (N, 64 cols); B fragments transient.
// Loader: 12 cp.async/thread = full 3 x 128 x 128B coverage (R12 bug fixed).
// ---------------------------------------------------------------------------
#define AMAT128 (128 * GPITCH)                // 18432
#define STG16_128 (3 * AMAT128)               // 55296
#define GEMM16_SMEM (2 * STG16_128)           // 110592

__global__ __launch_bounds__(256, 2) void gemm_f16_128(
    const __half* __restrict__ Ahi, const __half* __restrict__ Alo,
    const __half* __restrict__ Bf, float* __restrict__ Cf,
    int M, int N, int K, int swz)
{
    extern __shared__ char smem[];
    const uint32_t sb = smem_u32(smem);
    const int t = threadIdx.x;

    int bx = blockIdx.x, by = blockIdx.y;
    if (swz > 0) {
        int L   = by * gridDim.x + bx;
        int grp = swz * gridDim.y;
        int g   = L / grp, r = L % grp;
        bx = g * swz + (r % swz);
        by = r / swz;
    }
    const int bm = by * 128;
    const int bn = bx * 128;
    const int NK = K >> 6;
    const int lane = t & 31;
    const int w    = t >> 5;
    const int wm   = w & 3;          // 4 m-groups of 32 rows
    const int wn   = w >> 2;         // 2 n-groups of 64 cols

    // loader: 3 mats x 128 rows x 8 chunks of 16B; 12 chunks per thread
    const int lrow  = t >> 1;        // 0..127
    const int lhalf = t & 1;
    auto load_stage = [&](int s, int kt) {
        const int koff = kt * 64 + lhalf * 32;
        const uint32_t dst = sb + s * STG16_128 + lrow * GPITCH + lhalf * 64;
        const __half* pa0 = Ahi + (size_t)(bm + lrow) * K + koff;
        const __half* pa1 = Alo + (size_t)(bm + lrow) * K + koff;
        const __half* pb  = Bf  + (size_t)(bn + lrow) * K + koff;
        #pragma unroll
        for (int c = 0; c < 4; c++) {
            cpa16(dst + 0 * AMAT128 + c * 16, (const char*)pa0 + c * 16);
            cpa16(dst + 1 * AMAT128 + c * 16, (const char*)pa1 + c * 16);
            cpa16(dst + 2 * AMAT128 + c * 16, (const char*)pb  + c * 16);
        }
        CPA_COMMIT();
    };

    float acc[2][8][4];
    #pragma unroll
    for (int mt = 0; mt < 2; mt++)
        #pragma unroll
        for (int nt = 0; nt < 8; nt++)
            #pragma unroll
            for (int q = 0; q < 4; q++) acc[mt][nt][q] = 0.f;

    const uint32_t aOff = (uint32_t)((wm * 32 + (lane & 15)) * GPITCH + (lane >> 4) * 16);
    const uint32_t bOff = (uint32_t)((wn * 64 + (lane & 7) + (lane >> 4) * 8) * GPITCH
                                     + ((lane >> 3) & 1) * 16);

    load_stage(0, 0);

    for (int kt = 0; kt < NK; kt++) {
        const int s = kt & 1;
        asm volatile("cp.async.wait_group 0;" ::: "memory");
        __syncthreads();
        if (kt + 1 < NK) load_stage(s ^ 1, kt + 1);

        const uint32_t stg = sb + s * STG16_128;
        #pragma unroll
        for (int kk = 0; kk < 4; kk++) {
            uint32_t ah[2][4], al[2][4];
            #pragma unroll
            for (int mt = 0; mt < 2; mt++) {
                ldsm4(ah[mt], stg + 0 * AMAT128 + aOff + mt * (16 * GPITCH) + kk * 32);
                ldsm4(al[mt], stg + 1 * AMAT128 + aOff + mt * (16 * GPITCH) + kk * 32);
            }
            #pragma unroll
            for (int np = 0; np < 4; np++) {
                uint32_t bf[4];
                ldsm4(bf, stg + 2 * AMAT128 + bOff + np * (16 * GPITCH) + kk * 32);
                #pragma unroll
                for (int mt = 0; mt < 2; mt++)
                    #pragma unroll
                    for (int sub = 0; sub < 2; sub++)
                        mma_fp16(acc[mt][2 * np + sub], ah[mt], &bf[sub * 2]);
                #pragma unroll
                for (int mt = 0; mt < 2; mt++)
                    #pragma unroll
                    for (int sub = 0; sub < 2; sub++)
                        mma_fp16(acc[mt][2 * np + sub], al[mt], &bf[sub * 2]);
            }
        }
    }

    #pragma unroll
    for (int mt = 0; mt < 2; mt++) {
        const int row0 = bm + wm * 32 + mt * 16 + (lane >> 2);
        #pragma unroll
        for (int nt = 0; nt < 8; nt++) {
            const int col = bn + wn * 64 + nt * 8 + (lane & 3) * 2;
            #pragma unroll
            for (int half = 0; half < 2; half++) {
                const int row = row0 + half * 8;
                const size_t off = (size_t)row * N + col;
                float2 v;
                v.x = acc[mt][nt][half * 2 + 0];
                v.y = acc[mt][nt][half * 2 + 1];
                *(float2*)(Cf + off) = v;
            }
        }
    }
}

// ---------------------------------------------------------------------------
extern "C" void kernel_launch(void* const* d_in, const int* in_sizes, int n_in,
                              void* d_out, int out_size)
{
    const int*   idx     = (const int*)  d_in[0];
    const float* tok_emb = (const float*)d_in[1];
    const float* pos_emb = (const float*)d_in[2];
    const float* ln1_w   = (const float*)d_in[3];
    const float* ln1_b   = (const float*)d_in[4];
    const float* qkv_w   = (const float*)d_in[5];
    const float* out_w   = (const float*)d_in[6];
    const float* ln2_w   = (const float*)d_in[7];
    const float* ln2_b   = (const float*)d_in[8];
    const float* ff1_w   = (const float*)d_in[9];
    const float* ff2_w   = (const float*)d_in[10];
    const float* lnf_w   = (const float*)d_in[11];
    const float* lnf_b   = (const float*)d_in[12];
    float* out = (float*)d_out;

    float *x;
    __nv_bfloat16 *h_hi, *h_lo, *y_hi, *y_lo, *ff_hi, *ff_lo;
    __nv_bfloat16 *q_hi, *q_lo, *k_hi, *k_lo, *vt_hi, *vt_lo;
    __nv_bfloat16 *qkvT_hi, *qkvT_lo, *outT_hi, *outT_lo;
    __nv_bfloat16 *ff1T_hi, *ff1T_lo, *ff2T_hi, *ff2T_lo;
    __half *h16_hi, *h16_lo, *emb16;
    cudaGetSymbolAddress((void**)&x,       g_x);
    cudaGetSymbolAddress((void**)&h_hi,    g_h_hi);
    cudaGetSymbolAddress((void**)&h_lo,    g_h_lo);
    cudaGetSymbolAddress((void**)&y_hi,    g_y_hi);
    cudaGetSymbolAddress((void**)&y_lo,    g_y_lo);
    cudaGetSymbolAddress((void**)&ff_hi,   g_ff_hi);
    cudaGetSymbolAddress((void**)&ff_lo,   g_ff_lo);
    cudaGetSymbolAddress((void**)&q_hi,    g_q_hi);
    cudaGetSymbolAddress((void**)&q_lo,    g_q_lo);
    cudaGetSymbolAddress((void**)&k_hi,    g_k_hi);
    cudaGetSymbolAddress((void**)&k_lo,    g_k_lo);
    cudaGetSymbolAddress((void**)&vt_hi,   g_vt_hi);
    cudaGetSymbolAddress((void**)&vt_lo,   g_vt_lo);
    cudaGetSymbolAddress((void**)&qkvT_hi, g_qkvT_hi);
    cudaGetSymbolAddress((void**)&qkvT_lo, g_qkvT_lo);
    cudaGetSymbolAddress((void**)&outT_hi, g_outT_hi);
    cudaGetSymbolAddress((void**)&outT_lo, g_outT_lo);
    cudaGetSymbolAddress((void**)&ff1T_hi, g_ff1T_hi);
    cudaGetSymbolAddress((void**)&ff1T_lo, g_ff1T_lo);
    cudaGetSymbolAddress((void**)&ff2T_hi, g_ff2T_hi);
    cudaGetSymbolAddress((void**)&ff2T_lo, g_ff2T_lo);
    cudaGetSymbolAddress((void**)&h16_hi,  g_h16_hi);
    cudaGetSymbolAddress((void**)&h16_lo,  g_h16_lo);
    cudaGetSymbolAddress((void**)&emb16,   g_emb16);

    cudaFuncSetAttribute(flash_hmma3,
                         cudaFuncAttributeMaxDynamicSharedMemorySize, FLASH3_SMEM);
    cudaFuncSetAttribute(gemm_mma64<1>,
                         cudaFuncAttributeMaxDynamicSharedMemorySize, GEMM64_SMEM);
    cudaFuncSetAttribute(gemm_mma64<2>,
                         cudaFuncAttributeMaxDynamicSharedMemorySize, GEMM64_SMEM);
    cudaFuncSetAttribute(gemm_mma64<3>,
                         cudaFuncAttributeMaxDynamicSharedMemorySize, GEMM64_SMEM);
    cudaFuncSetAttribute(gemm_f16_128,
                         cudaFuncAttributeMaxDynamicSharedMemorySize, GEMM16_SMEM);

    // ---- weight prep (batched over layers) ----
    wprep_S16<<<8192, 256>>>((const float4*)tok_emb, emb16, VV * DD / 4);
    wprep_T<<<dim3(3*DD/32, DD/32, LL), 256>>>(qkv_w, qkvT_hi, qkvT_lo, DD, 3*DD);
    wprep_T<<<dim3(DD/32,   DD/32, LL), 256>>>(out_w, outT_hi, outT_lo, DD, DD);
    wprep_T<<<dim3(4*DD/32, DD/32, LL), 256>>>(ff1_w, ff1T_hi, ff1T_lo, DD, 4*DD);
    wprep_T<<<dim3(DD/32, 4*DD/32, LL), 256>>>(ff2_w, ff2T_hi, ff2T_lo, 4*DD, DD);

    embed_kernel<<<MM, 256>>>(idx, tok_emb, pos_emb, x);

    for (int l = 0; l < LL; l++) {
        ln_kernel<0><<<MM, 256>>>(x, ln1_w + l*DD, ln1_b + l*DD, h_hi, h_lo);
        gemm_mma64<3><<<dim3(3*DD/128, MM/64), 256, GEMM64_SMEM>>>(
            h_hi, h_lo, qkvT_hi + (size_t)l*3*DD*DD, qkvT_lo + (size_t)l*3*DD*DD,
            nullptr, nullptr, nullptr, nullptr,
            q_hi, q_lo, k_hi, k_lo, vt_hi, vt_lo, MM, 3*DD, DD);
        flash_hmma3<<<dim3(TT/128, HH, BB), 256, FLASH3_SMEM>>>(
            q_hi, q_lo, k_hi, k_lo, vt_hi, vt_lo, y_hi, y_lo);
        gemm_mma64<1><<<dim3(DD/128, MM/64), 256, GEMM64_SMEM>>>(
            y_hi, y_lo, outT_hi + (size_t)l*DD*DD, outT_lo + (size_t)l*DD*DD,
            x, x, nullptr, nullptr,
            nullptr, nullptr, nullptr, nullptr, nullptr, nullptr, MM, DD, DD);
        ln_kernel<0><<<MM, 256>>>(x, ln2_w + l*DD, ln2_b + l*DD, h_hi, h_lo);
        gemm_mma64<2><<<dim3(4*DD/128, MM/64), 256, GEMM64_SMEM>>>(
            h_hi, h_lo, ff1T_hi + (size_t)l*4*DD*DD, ff1T_lo + (size_t)l*4*DD*DD,
            nullptr, nullptr, ff_hi, ff_lo,
            nullptr, nullptr, nullptr, nullptr, nullptr, nullptr, MM, 4*DD, DD);
        gemm_mma64<1><<<dim3(DD/128, MM/64), 256, GEMM64_SMEM>>>(
            ff_hi, ff_lo, ff2T_hi + (size_t)l*4*DD*DD, ff2T_lo + (size_t)l*4*DD*DD,
            x, x, nullptr, nullptr,
            nullptr, nullptr, nullptr, nullptr, nullptr, nullptr, MM, DD, 4*DD);
    }

    ln_kernel<1><<<MM, 256>>>(x, lnf_w, lnf_b, h16_hi, h16_lo);
    gemm_f16_128<<<dim3(VV/128, MM/128), 256, GEMM16_SMEM>>>(
        h16_hi, h16_lo, emb16, out, MM, VV, DD, 25);
}

// round 14
// speedup vs baseline: 1.0516x; 1.0516x over previous
#include <cuda_runtime.h>
#include <cuda_bf16.h>
#include <cuda_fp16.h>
#include <math.h>
#include <stdint.h>

#define BB 2
#define TT 2048
#define LL 6
#define HH 12
#define DD 768
#define HDIM 64
#define VV 32000
#define MM (BB*TT)          // 4096 tokens

// ---------------------------------------------------------------------------
// Scratch (device globals; no allocation allowed)
// ---------------------------------------------------------------------------
__device__ float g_x  [MM * DD];            // residual stream (fp32)
__device__ float g_p0 [MM * DD];            // split-K partial 0 (fp32)
__device__ float g_p1 [MM * DD];            // split-K partial 1 (fp32)
__device__ __nv_bfloat16 g_h_hi[MM * DD],      g_h_lo[MM * DD];       // LN out split
__device__ __nv_bfloat16 g_y_hi[MM * DD],      g_y_lo[MM * DD];       // attn out split
__device__ __nv_bfloat16 g_ff_hi[MM * 4 * DD], g_ff_lo[MM * 4 * DD];  // gelu out split
// qkv split outputs (written by QKV GEMM epilogue)
__device__ __nv_bfloat16 g_q_hi[MM * DD],  g_q_lo[MM * DD];   // [tok][768]
__device__ __nv_bfloat16 g_k_hi[MM * DD],  g_k_lo[MM * DD];   // [tok][768]
__device__ __nv_bfloat16 g_vt_hi[MM * DD], g_vt_lo[MM * DD];  // [b,h][hd][tok]
// fp16 path for lm_head
__device__ __half g_h16_hi[MM * DD], g_h16_lo[MM * DD];
__device__ __half g_emb16[VV * DD];                            // [V][D] fp16
// transposed + split weights [N,K]
__device__ __nv_bfloat16 g_qkvT_hi[LL * 3 * DD * DD], g_qkvT_lo[LL * 3 * DD * DD];
__device__ __nv_bfloat16 g_outT_hi[LL * DD * DD],     g_outT_lo[LL * DD * DD];
__device__ __nv_bfloat16 g_ff1T_hi[LL * 4 * DD * DD], g_ff1T_lo[LL * 4 * DD * DD];
__device__ __nv_bfloat16 g_ff2T_hi[LL * 4 * DD * DD], g_ff2T_lo[LL * 4 * DD * DD];

// ---------------------------------------------------------------------------
// PTX helpers
// ---------------------------------------------------------------------------
__device__ __forceinline__ uint32_t smem_u32(const void* p) {
    uint32_t a;
    asm("{ .reg .u64 t; cvta.to.shared.u64 t, %1; cvt.u32.u64 %0, t; }"
        : "=r"(a) : "l"(p));
    return a;
}

__device__ __forceinline__ void cpa16(uint32_t dst, const void* src) {
    asm volatile("cp.async.cg.shared.global [%0], [%1], 16;" :: "r"(dst), "l"(src));
}
#define CPA_COMMIT() asm volatile("cp.async.commit_group;" ::: "memory")

__device__ __forceinline__ void ldsm4(uint32_t* r, uint32_t addr) {
    asm volatile("ldmatrix.sync.aligned.m8n8.x4.shared.b16 {%0,%1,%2,%3}, [%4];"
        : "=r"(r[0]), "=r"(r[1]), "=r"(r[2]), "=r"(r[3]) : "r"(addr));
}

__device__ __forceinline__ void mma_bf16(float* d, const uint32_t* a, const uint32_t* b) {
    asm volatile(
        "mma.sync.aligned.m16n8k16.row.col.f32.bf16.bf16.f32 "
        "{%0,%1,%2,%3}, {%4,%5,%6,%7}, {%8,%9}, {%0,%1,%2,%3};"
        : "+f"(d[0]), "+f"(d[1]), "+f"(d[2]), "+f"(d[3])
        : "r"(a[0]), "r"(a[1]), "r"(a[2]), "r"(a[3]), "r"(b[0]), "r"(b[1]));
}
__device__ __forceinline__ void mma_fp16(float* d, const uint32_t* a, const uint32_t* b) {
    asm volatile(
        "mma.sync.aligned.m16n8k16.row.col.f32.f16.f16.f32 "
        "{%0,%1,%2,%3}, {%4,%5,%6,%7}, {%8,%9}, {%0,%1,%2,%3};"
        : "+f"(d[0]), "+f"(d[1]), "+f"(d[2]), "+f"(d[3])
        : "r"(a[0]), "r"(a[1]), "r"(a[2]), "r"(a[3]), "r"(b[0]), "r"(b[1]));
}

__device__ __forceinline__ void split_bf(float v, __nv_bfloat16& hi, __nv_bfloat16& lo) {
    hi = __float2bfloat16(v);
    lo = __float2bfloat16(v - __bfloat162float(hi));
}
__device__ __forceinline__ uint32_t pack_bf2(float x, float y) {
    __nv_bfloat16 a = __float2bfloat16(x), b = __float2bfloat16(y);
    uint16_t ua = *(uint16_t*)&a, ub = *(uint16_t*)&b;
    return (uint32_t)ua | ((uint32_t)ub << 16);
}
__device__ __forceinline__ float bf_round(float x) {
    __nv_bfloat16 h = __float2bfloat16(x);
    return __bfloat162float(h);
}
__device__ __forceinline__ float gelu_exact(float v) {
    return 0.5f * v * (1.0f + erff(v * 0.70710678118654752f));
}

// ---------------------------------------------------------------------------
// Weight prep: transpose+split W[K,N] -> Thi/Tlo [N,K], batched over layers
// ---------------------------------------------------------------------------
__global__ __launch_bounds__(256) void wprep_T(
    const float* __restrict__ W, __nv_bfloat16* __restrict__ Thi,
    __nv_bfloat16* __restrict__ Tlo, int K, int N)
{
    __shared__ float tile[32][33];
    size_t lw = (size_t)blockIdx.z * K * N;
    const float* Wl = W + lw;
    __nv_bfloat16* Thl = Thi + lw;
    __nv_bfloat16* Tll = Tlo + lw;
    int n0 = blockIdx.x * 32, k0 = blockIdx.y * 32;
    int tx = threadIdx.x & 31, ty = threadIdx.x >> 5;
    #pragma unroll
    for (int i = ty; i < 32; i += 8)
        tile[i][tx] = Wl[(size_t)(k0 + i) * N + n0 + tx];
    __syncthreads();
    #pragma unroll
    for (int i = ty; i < 32; i += 8) {
        float v = tile[tx][i];
        size_t o = (size_t)(n0 + i) * K + k0 + tx;
        __nv_bfloat16 h, l; split_bf(v, h, l);
        Thl[o] = h; Tll[o] = l;
    }
}

// tok_emb -> fp16 (single rounding), for lm_head B operand
__global__ __launch_bounds__(256) void wprep_S16(
    const float4* __restrict__ W, __half* __restrict__ out, int n4)
{
    for (int i = blockIdx.x * blockDim.x + threadIdx.x; i < n4;
         i += gridDim.x * blockDim.x) {
        float4 v = W[i];
        ((__half2*)out)[i * 2    ] = __floats2half2_rn(v.x, v.y);
        ((__half2*)out)[i * 2 + 1] = __floats2half2_rn(v.z, v.w);
    }
}

// ---------------------------------------------------------------------------
// Embedding
// ---------------------------------------------------------------------------
__global__ __launch_bounds__(256) void embed_kernel(
    const int* __restrict__ idx, const float* __restrict__ tok_emb,
    const float* __restrict__ pos_emb, float* __restrict__ x)
{
    int tok = blockIdx.x;
    int id  = idx[tok];
    int p   = tok % TT;
    const float* te = tok_emb + (size_t)id * DD;
    const float* pe = pos_emb + (size_t)p  * DD;
    float* xr = x + (size_t)tok * DD;
    for (int d = threadIdx.x; d < DD; d += 256)
        xr[d] = te[d] + pe[d];
}

// ---------------------------------------------------------------------------
// LayerNorm with fused split-K reduction: if p0 != nullptr, x += p0 + p1
// (written back to x) before computing the LN. F16 selects output dtype.
// ---------------------------------------------------------------------------
template<int F16>
__global__ __launch_bounds__(256) void ln_kernel(
    const float* __restrict__ x, const float* __restrict__ p0,
    const float* __restrict__ p1, const float* __restrict__ w,
    const float* __restrict__ b, void* __restrict__ ohi_v,
    void* __restrict__ olo_v, float* __restrict__ xout)
{
    int tok = blockIdx.x;
    int t   = threadIdx.x;
    size_t base = (size_t)tok * DD;
    const float* xr = x + base;
    float v0 = xr[t], v1 = xr[t + 256], v2 = xr[t + 512];
    if (p0) {
        v0 += p0[base + t      ] + p1[base + t      ];
        v1 += p0[base + t + 256] + p1[base + t + 256];
        v2 += p0[base + t + 512] + p1[base + t + 512];
        xout[base + t      ] = v0;
        xout[base + t + 256] = v1;
        xout[base + t + 512] = v2;
    }
    float s  = v0 + v1 + v2;
    float s2 = v0*v0 + v1*v1 + v2*v2;
    #pragma unroll
    for (int off = 16; off; off >>= 1) {
        s  += __shfl_down_sync(0xffffffffu, s,  off);
        s2 += __shfl_down_sync(0xffffffffu, s2, off);
    }
    __shared__ float red[16];
    __shared__ float mean_s, rstd_s;
    int wid = t >> 5, lid = t & 31;
    if (lid == 0) { red[wid] = s; red[8 + wid] = s2; }
    __syncthreads();
    if (t == 0) {
        float S = 0.f, S2 = 0.f;
        #pragma unroll
        for (int i = 0; i < 8; i++) { S += red[i]; S2 += red[8 + i]; }
        float mean = S * (1.0f / DD);
        float var  = S2 * (1.0f / DD) - mean * mean;
        mean_s = mean;
        rstd_s = rsqrtf(var + 1e-5f);
    }
    __syncthreads();
    float mean = mean_s, rstd = rstd_s;
    #pragma unroll
    for (int q = 0; q < 3; q++) {
        int d = t + q * 256;
        float v = (q == 0 ? v0 : (q == 1 ? v1 : v2));
        float o = (v - mean) * rstd * w[d] + b[d];
        if (F16) {
            __half h = __float2half(o);
            __half l = __float2half(o - __half2float(h));
            ((__half*)ohi_v)[base + d] = h;
            ((__half*)olo_v)[base + d] = l;
        } else {
            __nv_bfloat16 h, l; split_bf(o, h, l);
            ((__nv_bfloat16*)ohi_v)[base + d] = h;
            ((__nv_bfloat16*)olo_v)[base + d] = l;
        }
    }
}

// ---------------------------------------------------------------------------
// Flash attention on HMMA, Q-tile = 128 rows (256 threads, 8 warps x 16 rows).
// K/V tiles 64 rows, double-buffered. 2 CTAs/SM. (R11 verified)
// ---------------------------------------------------------------------------
#define FP2 144
#define FMQ (128 * FP2)            // Q mat: 18432
#define FMK (64 * FP2)             // K/V mat: 9216
#define FLASH3_SMEM (2 * FMQ + 8 * FMK)   // 110592

__global__ __launch_bounds__(256, 2) void flash_hmma3(
    const __nv_bfloat16* __restrict__ q_hi, const __nv_bfloat16* __restrict__ q_lo,
    const __nv_bfloat16* __restrict__ k_hi, const __nv_bfloat16* __restrict__ k_lo,
    const __nv_bfloat16* __restrict__ vt_hi, const __nv_bfloat16* __restrict__ vt_lo,
    __nv_bfloat16* __restrict__ y_hi, __nv_bfloat16* __restrict__ y_lo)
{
    extern __shared__ char fsm[];
    const uint32_t sb  = smem_u32(fsm);
    const uint32_t sQh = sb, sQl = sb + FMQ;
    const uint32_t sKV = sb + 2 * FMQ;

    const int qt = blockIdx.x, hh = blockIdx.y, b = blockIdx.z;
    const int t = threadIdx.x, lane = t & 31, w = t >> 5;
    const unsigned FULL = 0xffffffffu;
    const int NKT = 2 * qt + 2;    // k-tiles for this q-tile

    {
        const __nv_bfloat16* srcs[2] = {q_hi, q_lo};
        #pragma unroll
        for (int m2 = 0; m2 < 2; m2++) {
            #pragma unroll
            for (int j = 0; j < 4; j++) {
                int id = t * 4 + j;
                int r = id >> 3, c = id & 7;
                int tok = b * TT + qt * 128 + r;
                cpa16(sb + m2 * FMQ + r * FP2 + c * 16,
                      srcs[m2] + (size_t)tok * DD + hh * HDIM + c * 8);
            }
        }
        CPA_COMMIT();
    }
    auto load_kv = [&](int s, int kt) {
        const uint32_t base = sKV + s * (4 * FMK);
        #pragma unroll
        for (int j = 0; j < 2; j++) {
            int id = t * 2 + j;
            int r = id >> 3, c = id & 7;
            int tok = b * TT + kt * 64 + r;
            size_t koff = (size_t)tok * DD + hh * HDIM + c * 8;
            cpa16(base + 0 * FMK + r * FP2 + c * 16, k_hi + koff);
            cpa16(base + 1 * FMK + r * FP2 + c * 16, k_lo + koff);
            size_t voff = ((size_t)(b * HH + hh) * HDIM + r) * TT + kt * 64 + c * 8;
            cpa16(base + 2 * FMK + r * FP2 + c * 16, vt_hi + voff);
            cpa16(base + 3 * FMK + r * FP2 + c * 16, vt_lo + voff);
        }
        CPA_COMMIT();
    };

    float m[2] = {-1e30f, -1e30f}, l[2] = {0.f, 0.f};
    float O[8][4];
    #pragma unroll
    for (int nt = 0; nt < 8; nt++)
        #pragma unroll
        for (int e = 0; e < 4; e++) O[nt][e] = 0.f;

    const uint32_t aOff = (uint32_t)((w * 16 + (lane & 15)) * FP2 + (lane >> 4) * 16);
    const uint32_t bOff = (uint32_t)(((lane & 7) + (lane >> 4) * 8) * FP2
                                     + ((lane >> 3) & 1) * 16);

    load_kv(0, 0);

    for (int kt = 0; kt < NKT; kt++) {
        asm volatile("cp.async.wait_group 0;" ::: "memory");
        __syncthreads();
        if (kt + 1 < NKT) load_kv((kt + 1) & 1, kt + 1);

        const uint32_t bK = sKV + (kt & 1) * (4 * FMK);

        float S[8][4];
        #pragma unroll
        for (int nt = 0; nt < 8; nt++)
            #pragma unroll
            for (int e = 0; e < 4; e++) S[nt][e] = 0.f;

        #pragma unroll
        for (int kk = 0; kk < 4; kk++) {
            uint32_t qh[4], ql[4];
            ldsm4(qh, sQh + aOff + kk * 32);
            ldsm4(ql, sQl + aOff + kk * 32);
            #pragma unroll
            for (int np = 0; np < 4; np++) {
                uint32_t kh[4], kl[4];
                ldsm4(kh, bK + 0 * FMK + bOff + np * (16 * FP2) + kk * 32);
                ldsm4(kl, bK + 1 * FMK + bOff + np * (16 * FP2) + kk * 32);
                #pragma unroll
                for (int sub = 0; sub < 2; sub++)
                    mma_bf16(S[2 * np + sub], qh, &kh[sub * 2]);
                #pragma unroll
                for (int sub = 0; sub < 2; sub++)
                    mma_bf16(S[2 * np + sub], qh, &kl[sub * 2]);
                #pragma unroll
                for (int sub = 0; sub < 2; sub++)
                    mma_bf16(S[2 * np + sub], ql, &kh[sub * 2]);
            }
        }

        if (kt >= 2 * qt) {
            #pragma unroll
            for (int nt = 0; nt < 8; nt++)
                #pragma unroll
                for (int e = 0; e < 4; e++) {
                    int col = kt * 64 + nt * 8 + (lane & 3) * 2 + (e & 1);
                    int row = qt * 128 + w * 16 + (lane >> 2) + (e >> 1) * 8;
                    S[nt][e] = (col > row) ? -1e30f : S[nt][e] * 0.125f;
                }
        } else {
            #pragma unroll
            for (int nt = 0; nt < 8; nt++)
                #pragma unroll
                for (int e = 0; e < 4; e++) S[nt][e] *= 0.125f;
        }

        float a[2];
        #pragma unroll
        for (int h = 0; h < 2; h++) {
            float mx = -1e30f;
            #pragma unroll
            for (int nt = 0; nt < 8; nt++)
                mx = fmaxf(mx, fmaxf(S[nt][2 * h], S[nt][2 * h + 1]));
            mx = fmaxf(mx, __shfl_xor_sync(FULL, mx, 1));
            mx = fmaxf(mx, __shfl_xor_sync(FULL, mx, 2));
            float mn = fmaxf(m[h], mx);
            a[h] = __expf(m[h] - mn);
            float sum = 0.f;
            #pragma unroll
            for (int nt = 0; nt < 8; nt++) {
                float p0 = __expf(S[nt][2 * h    ] - mn);
                float p1 = __expf(S[nt][2 * h + 1] - mn);
                S[nt][2 * h] = p0; S[nt][2 * h + 1] = p1;
                sum += p0 + p1;
            }
            sum += __shfl_xor_sync(FULL, sum, 1);
            sum += __shfl_xor_sync(FULL, sum, 2);
            l[h] = l[h] * a[h] + sum;
            m[h] = mn;
        }
        #pragma unroll
        for (int nt = 0; nt < 8; nt++) {
            O[nt][0] *= a[0]; O[nt][1] *= a[0];
            O[nt][2] *= a[1]; O[nt][3] *= a[1];
        }

        #pragma unroll
        for (int kb = 0; kb < 4; kb++) {
            uint32_t pah[4], pal[4];
            {
                float x0 = S[2*kb][0], x1 = S[2*kb][1], x2 = S[2*kb][2], x3 = S[2*kb][3];
                float y0 = S[2*kb+1][0], y1 = S[2*kb+1][1], y2 = S[2*kb+1][2], y3 = S[2*kb+1][3];
                float hx0 = bf_round(x0), hx1 = bf_round(x1), hx2 = bf_round(x2), hx3 = bf_round(x3);
                float hy0 = bf_round(y0), hy1 = bf_round(y1), hy2 = bf_round(y2), hy3 = bf_round(y3);
                pah[0] = pack_bf2(hx0, hx1); pah[1] = pack_bf2(hx2, hx3);
                pah[2] = pack_bf2(hy0, hy1); pah[3] = pack_bf2(hy2, hy3);
                pal[0] = pack_bf2(x0 - hx0, x1 - hx1); pal[1] = pack_bf2(x2 - hx2, x3 - hx3);
                pal[2] = pack_bf2(y0 - hy0, y1 - hy1); pal[3] = pack_bf2(y2 - hy2, y3 - hy3);
            }
            #pragma unroll
            for (int np = 0; np < 4; np++) {
                uint32_t vh[4], vl[4];
                ldsm4(vh, bK + 2 * FMK + bOff + np * (16 * FP2) + kb * 32);
                ldsm4(vl, bK + 3 * FMK + bOff + np * (16 * FP2) + kb * 32);
                #pragma unroll
                for (int sub = 0; sub < 2; sub++)
                    mma_bf16(O[2 * np + sub], pah, &vh[sub * 2]);
                #pragma unroll
                for (int sub = 0; sub < 2; sub++)
                    mma_bf16(O[2 * np + sub], pah, &vl[sub * 2]);
                #pragma unroll
                for (int sub = 0; sub < 2; sub++)
                    mma_bf16(O[2 * np + sub], pal, &vh[sub * 2]);
            }
        }
    }

    float inv[2] = {1.0f / l[0], 1.0f / l[1]};
    #pragma unroll
    for (int nt = 0; nt < 8; nt++) {
        int col = nt * 8 + (lane & 3) * 2;
        #pragma unroll
        for (int h = 0; h < 2; h++) {
            int row = qt * 128 + w * 16 + (lane >> 2) + h * 8;
            int tok = b * TT + row;
            size_t base = (size_t)tok * DD + hh * HDIM + col;
            float v0 = O[nt][2 * h    ] * inv[h];
            float v1 = O[nt][2 * h + 1] * inv[h];
            float h0 = bf_round(v0), h1 = bf_round(v1);
            *(uint32_t*)((char*)y_hi + base * 2) = pack_bf2(h0, h1);
            *(uint32_t*)((char*)y_lo + base * 2) = pack_bf2(v0 - h0, v1 - h1);
        }
    }
}

// ---------------------------------------------------------------------------
// HMMA GEMM 64x128 tile (bf16 3-term split). 8 warps: 2(M) x 4(N). 2 CTAs/SM.
// EPI: 0 = split-K partial store (grid.y = 2*M/64; half 0->Cf0, half 1->Cf1);
//      2 = gelu->split; 3 = qkv split/route. Khalf = K-extent per CTA.
// ---------------------------------------------------------------------------
#define GPITCH 144
#define AMAT64 (64 * GPITCH)                 // 9216
#define BMAT64 (128 * GPITCH)                // 18432
#define STG64  (2 * AMAT64 + 2 * BMAT64)     // 55296
#define GEMM64_SMEM (2 * STG64)              // 110592

template<int EPI>
__global__ __launch_bounds__(256, 1) void gemm_mma64(
    const __nv_bfloat16* __restrict__ Ahi, const __nv_bfloat16* __restrict__ Alo,
    const __nv_bfloat16* __restrict__ Bhi, const __nv_bfloat16* __restrict__ Blo,
    float* __restrict__ Cf0, float* __restrict__ Cf1,
    __nv_bfloat16* __restrict__ Chi, __nv_bfloat16* __restrict__ Clo,
    __nv_bfloat16* __restrict__ Qh, __nv_bfloat16* __restrict__ Ql,
    __nv_bfloat16* __restrict__ Kh, __nv_bfloat16* __restrict__ Kl,
    __nv_bfloat16* __restrict__ Vth, __nv_bfloat16* __restrict__ Vtl,
    int M, int N, int K, int Khalf)
{
    extern __shared__ char smem[];
    const uint32_t sb = smem_u32(smem);
    const int t = threadIdx.x;

    const int mtiles = M >> 6;
    const int half   = blockIdx.y / mtiles;          // 0 except split-K upper
    const int bm     = (blockIdx.y % mtiles) * 64;
    const int bn     = blockIdx.x * 128;
    const int k0     = half * Khalf;
    Ahi += k0; Alo += k0; Bhi += k0; Blo += k0;
    const int NK = Khalf >> 6;
    const int lane = t & 31;
    const int w    = t >> 5;
    const int wm   = w & 1;
    const int wn   = w >> 1;

    const int rbase = t >> 3;
    const int cc    = t & 7;
    auto load_stage = [&](int s, int kt) {
        const int koff = kt * 64 + cc * 8;
        const uint32_t stg = sb + s * STG64;
        #pragma unroll
        for (int i = 0; i < 2; i++) {
            int r = rbase + 32 * i;
            cpa16(stg + r * GPITCH + cc * 16, Ahi + (size_t)(bm + r) * K + koff);
        }
        #pragma unroll
        for (int i = 0; i < 2; i++) {
            int r = rbase + 32 * i;
            cpa16(stg + AMAT64 + r * GPITCH + cc * 16, Alo + (size_t)(bm + r) * K + koff);
        }
        #pragma unroll
        for (int i = 0; i < 4; i++) {
            int r = rbase + 32 * i;
            cpa16(stg + 2 * AMAT64 + r * GPITCH + cc * 16, Bhi + (size_t)(bn + r) * K + koff);
        }
        #pragma unroll
        for (int i = 0; i < 4; i++) {
            int r = rbase + 32 * i;
            cpa16(stg + 2 * AMAT64 + BMAT64 + r * GPITCH + cc * 16,
                  Blo + (size_t)(bn + r) * K + koff);
        }
        CPA_COMMIT();
    };

    float acc[2][4][4];
    #pragma unroll
    for (int mt = 0; mt < 2; mt++)
        #pragma unroll
        for (int nt = 0; nt < 4; nt++)
            #pragma unroll
            for (int q = 0; q < 4; q++) acc[mt][nt][q] = 0.f;

    const uint32_t aOff = (uint32_t)((wm * 32 + (lane & 15)) * GPITCH + (lane >> 4) * 16);
    const uint32_t bOff = (uint32_t)((wn * 32 + (lane & 7) + (lane >> 4) * 8) * GPITCH
                                     + ((lane >> 3) & 1) * 16);

    load_stage(0, 0);

    for (int kt = 0; kt < NK; kt++) {
        const int s = kt & 1;
        asm volatile("cp.async.wait_group 0;" ::: "memory");
        __syncthreads();
        if (kt + 1 < NK) load_stage(s ^ 1, kt + 1);

        const uint32_t stg = sb + s * STG64;
        #pragma unroll
        for (int kk = 0; kk < 4; kk++) {
            uint32_t ah[2][4], al[2][4], bh[2][4], bl[2][4];
            #pragma unroll
            for (int mt = 0; mt < 2; mt++) {
                ldsm4(ah[mt], stg + aOff + mt * (16 * GPITCH) + kk * 32);
                ldsm4(al[mt], stg + AMAT64 + aOff + mt * (16 * GPITCH) + kk * 32);
            }
            #pragma unroll
            for (int np = 0; np < 2; np++) {
                ldsm4(bh[np], stg + 2 * AMAT64 + bOff + np * (16 * GPITCH) + kk * 32);
                ldsm4(bl[np], stg + 2 * AMAT64 + BMAT64 + bOff + np * (16 * GPITCH) + kk * 32);
            }
            #pragma unroll
            for (int mt = 0; mt < 2; mt++)
                #pragma unroll
                for (int nt = 0; nt < 4; nt++)
                    mma_bf16(acc[mt][nt], ah[mt], &bh[nt >> 1][(nt & 1) * 2]);
            #pragma unroll
            for (int mt = 0; mt < 2; mt++)
                #pragma unroll
                for (int nt = 0; nt < 4; nt++)
                    mma_bf16(acc[mt][nt], ah[mt], &bl[nt >> 1][(nt & 1) * 2]);
            #pragma unroll
            for (int mt = 0; mt < 2; mt++)
                #pragma unroll
                for (int nt = 0; nt < 4; nt++)
                    mma_bf16(acc[mt][nt], al[mt], &bh[nt >> 1][(nt & 1) * 2]);
        }
    }

    float* dst = half ? Cf1 : Cf0;
    #pragma unroll
    for (int mt = 0; mt < 2; mt++) {
        const int row0 = bm + wm * 32 + mt * 16 + (lane >> 2);
        #pragma unroll
        for (int nt = 0; nt < 4; nt++) {
            const int col = bn + wn * 32 + nt * 8 + (lane & 3) * 2;
            #pragma unroll
            for (int half2 = 0; half2 < 2; half2++) {
                const int row = row0 + half2 * 8;
                const float v0 = acc[mt][nt][half2 * 2 + 0];
                const float v1 = acc[mt][nt][half2 * 2 + 1];
                const size_t off = (size_t)row * N + col;
                if (EPI == 0) {
                    float2 v; v.x = v0; v.y = v1;
                    *(float2*)(dst + off) = v;
                } else if (EPI == 2) {
                    float g0 = gelu_exact(v0), g1 = gelu_exact(v1);
                    float h0 = bf_round(g0), h1 = bf_round(g1);
                    *(uint32_t*)((char*)Chi + off * 2) = pack_bf2(h0, h1);
                    *(uint32_t*)((char*)Clo + off * 2) = pack_bf2(g0 - h0, g1 - h1);
                } else {  // EPI == 3: qkv split + route
                    float h0 = bf_round(v0), h1 = bf_round(v1);
                    if (bn < DD) {
                        size_t o2 = ((size_t)row * DD + col) * 2;
                        *(uint32_t*)((char*)Qh + o2) = pack_bf2(h0, h1);
                        *(uint32_t*)((char*)Ql + o2) = pack_bf2(v0 - h0, v1 - h1);
                    } else if (bn < 2 * DD) {
                        size_t o2 = ((size_t)row * DD + (col - DD)) * 2;
                        *(uint32_t*)((char*)Kh + o2) = pack_bf2(h0, h1);
                        *(uint32_t*)((char*)Kl + o2) = pack_bf2(v0 - h0, v1 - h1);
                    } else {
                        int c  = col - 2 * DD;
                        int hq = c >> 6, hd = c & 63;
                        int bb2 = row >> 11, tt2 = row & 2047;
                        size_t a0 = ((size_t)(bb2 * HH + hq) * HDIM + hd) * TT + tt2;
                        __nv_bfloat16 hb0 = __float2bfloat16(h0);
                        __nv_bfloat16 hb1 = __float2bfloat16(h1);
                        __nv_bfloat16 lb0 = __float2bfloat16(v0 - h0);
                        __nv_bfloat16 lb1 = __float2bfloat16(v1 - h1);
                        Vth[a0]      = hb0; Vtl[a0]      = lb0;
                        Vth[a0 + TT] = hb1; Vtl[a0 + TT] = lb1;
                    }
                }
            }
        }
    }
}

// ---------------------------------------------------------------------------
// lm_head GEMM: fp16 2-term split, 64x128 tile, group swizzle. (R11 verified)
// ---------------------------------------------------------------------------
#define STG16_64 (2 * AMAT64 + BMAT64)        // 36864
#define GEMM16_SMEM (2 * STG16_64)            // 73728

__global__ __launch_bounds__(256, 1) void gemm_f16_64(
    const __half* __restrict__ Ahi, const __half* __restrict__ Alo,
    const __half* __restrict__ Bf, float* __restrict__ Cf,
    int M, int N, int K, int swz)
{
    extern __shared__ char smem[];
    const uint32_t sb = smem_u32(smem);
    const int t = threadIdx.x;

    int bx = blockIdx.x, by = blockIdx.y;
    if (swz > 0) {
        int L   = by * gridDim.x + bx;
        int grp = swz * gridDim.y;
        int g   = L / grp, r = L % grp;
        bx = g * swz + (r % swz);
        by = r / swz;
    }
    const int bm = by * 64;
    const int bn = bx * 128;
    const int NK = K >> 6;
    const int lane = t & 31;
    const int w    = t >> 5;
    const int wm   = w & 1;
    const int wn   = w >> 1;

    const int rbase = t >> 3;
    const int cc    = t & 7;
    auto load_stage = [&](int s, int kt) {
        const int koff = kt * 64 + cc * 8;
        const uint32_t stg = sb + s * STG16_64;
        #pragma unroll
        for (int i = 0; i < 2; i++) {
            int r = rbase + 32 * i;
            cpa16(stg + r * GPITCH + cc * 16, Ahi + (size_t)(bm + r) * K + koff);
        }
        #pragma unroll
        for (int i = 0; i < 2; i++) {
            int r = rbase + 32 * i;
            cpa16(stg + AMAT64 + r * GPITCH + cc * 16, Alo + (size_t)(bm + r) * K + koff);
        }
        #pragma unroll
        for (int i = 0; i < 4; i++) {
            int r = rbase + 32 * i;
            cpa16(stg + 2 * AMAT64 + r * GPITCH + cc * 16, Bf + (size_t)(bn + r) * K + koff);
        }
        CPA_COMMIT();
    };

    float acc[2][4][4];
    #pragma unroll
    for (int mt = 0; mt < 2; mt++)
        #pragma unroll
        for (int nt = 0; nt < 4; nt++)
            #pragma unroll
            for (int q = 0; q < 4; q++) acc[mt][nt][q] = 0.f;

    const uint32_t aOff = (uint32_t)((wm * 32 + (lane & 15)) * GPITCH + (lane >> 4) * 16);
    const uint32_t bOff = (uint32_t)((wn * 32 + (lane & 7) + (lane >> 4) * 8) * GPITCH
                                     + ((lane >> 3) & 1) * 16);

    load_stage(0, 0);

    for (int kt = 0; kt < NK; kt++) {
        const int s = kt & 1;
        asm volatile("cp.async.wait_group 0;" ::: "memory");
        __syncthreads();
        if (kt + 1 < NK) load_stage(s ^ 1, kt + 1);

        const uint32_t stg = sb + s * STG16_64;
        #pragma unroll
        for (int kk = 0; kk < 4; kk++) {
            uint32_t ah[2][4], al[2][4], bf[2][4];
            #pragma unroll
            for (int mt = 0; mt < 2; mt++) {
                ldsm4(ah[mt], stg + aOff + mt * (16 * GPITCH) + kk * 32);
                ldsm4(al[mt], stg + AMAT64 + aOff + mt * (16 * GPITCH) + kk * 32);
            }
            #pragma unroll
            for (int np = 0; np < 2; np++)
                ldsm4(bf[np], stg + 2 * AMAT64 + bOff + np * (16 * GPITCH) + kk * 32);
            #pragma unroll
            for (int mt = 0; mt < 2; mt++)
                #pragma unroll
                for (int nt = 0; nt < 4; nt++)
                    mma_fp16(acc[mt][nt], ah[mt], &bf[nt >> 1][(nt & 1) * 2]);
            #pragma unroll
            for (int mt = 0; mt < 2; mt++)
                #pragma unroll
                for (int nt = 0; nt < 4; nt++)
                    mma_fp16(acc[mt][nt], al[mt], &bf[nt >> 1][(nt & 1) * 2]);
        }
    }

    #pragma unroll
    for (int mt = 0; mt < 2; mt++) {
        const int row0 = bm + wm * 32 + mt * 16 + (lane >> 2);
        #pragma unroll
        for (int nt = 0; nt < 4; nt++) {
            const int col = bn + wn * 32 + nt * 8 + (lane & 3) * 2;
            #pragma unroll
            for (int half = 0; half < 2; half++) {
                const int row = row0 + half * 8;
                const size_t off = (size_t)row * N + col;
                float2 v;
                v.x = acc[mt][nt][half * 2 + 0];
                v.y = acc[mt][nt][half * 2 + 1];
                *(float2*)(Cf + off) = v;
            }
        }
    }
}

// ---------------------------------------------------------------------------
extern "C" void kernel_launch(void* const* d_in, const int* in_sizes, int n_in,
                              void* d_out, int out_size)
{
    const int*   idx     = (const int*)  d_in[0];
    const float* tok_emb = (const float*)d_in[1];
    const float* pos_emb = (const float*)d_in[2];
    const float* ln1_w   = (const float*)d_in[3];
    const float* ln1_b   = (const float*)d_in[4];
    const float* qkv_w   = (const float*)d_in[5];
    const float* out_w   = (const float*)d_in[6];
    const float* ln2_w   = (const float*)d_in[7];
    const float* ln2_b   = (const float*)d_in[8];
    const float* ff1_w   = (const float*)d_in[9];
    const float* ff2_w   = (const float*)d_in[10];
    const float* lnf_w   = (const float*)d_in[11];
    const float* lnf_b   = (const float*)d_in[12];
    float* out = (float*)d_out;

    float *x, *p0, *p1;
    __nv_bfloat16 *h_hi, *h_lo, *y_hi, *y_lo, *ff_hi, *ff_lo;
    __nv_bfloat16 *q_hi, *q_lo, *k_hi, *k_lo, *vt_hi, *vt_lo;
    __nv_bfloat16 *qkvT_hi, *qkvT_lo, *outT_hi, *outT_lo;
    __nv_bfloat16 *ff1T_hi, *ff1T_lo, *ff2T_hi, *ff2T_lo;
    __half *h16_hi, *h16_lo, *emb16;
    cudaGetSymbolAddress((void**)&x,       g_x);
    cudaGetSymbolAddress((void**)&p0,      g_p0);
    cudaGetSymbolAddress((void**)&p1,      g_p1);
    cudaGetSymbolAddress((void**)&h_hi,    g_h_hi);
    cudaGetSymbolAddress((void**)&h_lo,    g_h_lo);
    cudaGetSymbolAddress((void**)&y_hi,    g_y_hi);
    cudaGetSymbolAddress((void**)&y_lo,    g_y_lo);
    cudaGetSymbolAddress((void**)&ff_hi,   g_ff_hi);
    cudaGetSymbolAddress((void**)&ff_lo,   g_ff_lo);
    cudaGetSymbolAddress((void**)&q_hi,    g_q_hi);
    cudaGetSymbolAddress((void**)&q_lo,    g_q_lo);
    cudaGetSymbolAddress((void**)&k_hi,    g_k_hi);
    cudaGetSymbolAddress((void**)&k_lo,    g_k_lo);
    cudaGetSymbolAddress((void**)&vt_hi,   g_vt_hi);
    cudaGetSymbolAddress((void**)&vt_lo,   g_vt_lo);
    cudaGetSymbolAddress((void**)&qkvT_hi, g_qkvT_hi);
    cudaGetSymbolAddress((void**)&qkvT_lo, g_qkvT_lo);
    cudaGetSymbolAddress((void**)&outT_hi, g_outT_hi);
    cudaGetSymbolAddress((void**)&outT_lo, g_outT_lo);
    cudaGetSymbolAddress((void**)&ff1T_hi, g_ff1T_hi);
    cudaGetSymbolAddress((void**)&ff1T_lo, g_ff1T_lo);
    cudaGetSymbolAddress((void**)&ff2T_hi, g_ff2T_hi);
    cudaGetSymbolAddress((void**)&ff2T_lo, g_ff2T_lo);
    cudaGetSymbolAddress((void**)&h16_hi,  g_h16_hi);
    cudaGetSymbolAddress((void**)&h16_lo,  g_h16_lo);
    cudaGetSymbolAddress((void**)&emb16,   g_emb16);

    cudaFuncSetAttribute(flash_hmma3,
                         cudaFuncAttributeMaxDynamicSharedMemorySize, FLASH3_SMEM);
    cudaFuncSetAttribute(gemm_mma64<0>,
                         cudaFuncAttributeMaxDynamicSharedMemorySize, GEMM64_SMEM);
    cudaFuncSetAttribute(gemm_mma64<2>,
                         cudaFuncAttributeMaxDynamicSharedMemorySize, GEMM64_SMEM);
    cudaFuncSetAttribute(gemm_mma64<3>,
                         cudaFuncAttributeMaxDynamicSharedMemorySize, GEMM64_SMEM);
    cudaFuncSetAttribute(gemm_f16_64,
                         cudaFuncAttributeMaxDynamicSharedMemorySize, GEMM16_SMEM);

    // ---- weight prep (batched over layers) ----
    wprep_S16<<<8192, 256>>>((const float4*)tok_emb, emb16, VV * DD / 4);
    wprep_T<<<dim3(3*DD/32, DD/32, LL), 256>>>(qkv_w, qkvT_hi, qkvT_lo, DD, 3*DD);
    wprep_T<<<dim3(DD/32,   DD/32, LL), 256>>>(out_w, outT_hi, outT_lo, DD, DD);
    wprep_T<<<dim3(4*DD/32, DD/32, LL), 256>>>(ff1_w, ff1T_hi, ff1T_lo, DD, 4*DD);
    wprep_T<<<dim3(DD/32, 4*DD/32, LL), 256>>>(ff2_w, ff2T_hi, ff2T_lo, 4*DD, DD);

    embed_kernel<<<MM, 256>>>(idx, tok_emb, pos_emb, x);

    for (int l = 0; l < LL; l++) {
        // ln1: fused add of previous layer's ff2 partials (none for layer 0)
        ln_kernel<0><<<MM, 256>>>(x, (l == 0) ? nullptr : p0, p1,
                                  ln1_w + l*DD, ln1_b + l*DD, h_hi, h_lo, x);
        gemm_mma64<3><<<dim3(3*DD/128, MM/64), 256, GEMM64_SMEM>>>(
            h_hi, h_lo, qkvT_hi + (size_t)l*3*DD*DD, qkvT_lo + (size_t)l*3*DD*DD,
            nullptr, nullptr, nullptr, nullptr,
            q_hi, q_lo, k_hi, k_lo, vt_hi, vt_lo, MM, 3*DD, DD, DD);
        flash_hmma3<<<dim3(TT/128, HH, BB), 256, FLASH3_SMEM>>>(
            q_hi, q_lo, k_hi, k_lo, vt_hi, vt_lo, y_hi, y_lo);
        // out-proj: split-K=2 into partials
        gemm_mma64<0><<<dim3(DD/128, 2*MM/64), 256, GEMM64_SMEM>>>(
            y_hi, y_lo, outT_hi + (size_t)l*DD*DD, outT_lo + (size_t)l*DD*DD,
            p0, p1, nullptr, nullptr,
            nullptr, nullptr, nullptr, nullptr, nullptr, nullptr,
            MM, DD, DD, DD/2);
        // ln2: fused x += p0+p1
        ln_kernel<0><<<MM, 256>>>(x, p0, p1,
                                  ln2_w + l*DD, ln2_b + l*DD, h_hi, h_lo, x);
        gemm_mma64<2><<<dim3(4*DD/128, MM/64), 256, GEMM64_SMEM>>>(
            h_hi, h_lo, ff1T_hi + (size_t)l*4*DD*DD, ff1T_lo + (size_t)l*4*DD*DD,
            nullptr, nullptr, ff_hi, ff_lo,
            nullptr, nullptr, nullptr, nullptr, nullptr, nullptr,
            MM, 4*DD, DD, DD);
        // ff2: split-K=2 into partials (folded into next ln1 / lnf)
        gemm_mma64<0><<<dim3(DD/128, 2*MM/64), 256, GEMM64_SMEM>>>(
            ff_hi, ff_lo, ff2T_hi + (size_t)l*4*DD*DD, ff2T_lo + (size_t)l*4*DD*DD,
            p0, p1, nullptr, nullptr,
            nullptr, nullptr, nullptr, nullptr, nullptr, nullptr,
            MM, DD, 4*DD, 2*DD);
    }

    // lnf: fused x += p0+p1 from the last ff2
    ln_kernel<1><<<MM, 256>>>(x, p0, p1, lnf_w, lnf_b, h16_hi, h16_lo, x);
    gemm_f16_64<<<dim3(VV/128, MM/64), 256, GEMM16_SMEM>>>(
        h16_hi, h16_lo, emb16, out, MM, VV, DD, 25);
}

// round 15
// speedup vs baseline: 1.0553x; 1.0036x over previous
#include <cuda_runtime.h>
#include <cuda_bf16.h>
#include <cuda_fp16.h>
#include <math.h>
#include <stdint.h>

#define BB 2
#define TT 2048
#define LL 6
#define HH 12
#define DD 768
#define HDIM 64
#define VV 32000
#define MM (BB*TT)          // 4096 tokens

// ---------------------------------------------------------------------------
// Scratch (device globals; no allocation allowed)
// ---------------------------------------------------------------------------
__device__ float g_x  [MM * DD];            // residual stream (fp32)
__device__ float g_p0 [MM * DD];            // split-K partial 0 (fp32)
__device__ float g_p1 [MM * DD];            // split-K partial 1 (fp32)
__device__ __nv_bfloat16 g_h_hi[MM * DD],      g_h_lo[MM * DD];       // LN out split
__device__ __nv_bfloat16 g_y_hi[MM * DD],      g_y_lo[MM * DD];       // attn out split
__device__ __nv_bfloat16 g_ff_hi[MM * 4 * DD], g_ff_lo[MM * 4 * DD];  // gelu out split
// qkv split outputs (written by QKV GEMM epilogue)
__device__ __nv_bfloat16 g_q_hi[MM * DD],  g_q_lo[MM * DD];   // [tok][768]
__device__ __nv_bfloat16 g_k_hi[MM * DD],  g_k_lo[MM * DD];   // [tok][768]
__device__ __nv_bfloat16 g_vt_hi[MM * DD], g_vt_lo[MM * DD];  // [b,h][hd][tok]
// fp16 path for lm_head
__device__ __half g_h16_hi[MM * DD], g_h16_lo[MM * DD];
__device__ __half g_emb16[VV * DD];                            // [V][D] fp16
// transposed + split weights [N,K]
__device__ __nv_bfloat16 g_qkvT_hi[LL * 3 * DD * DD], g_qkvT_lo[LL * 3 * DD * DD];
__device__ __nv_bfloat16 g_outT_hi[LL * DD * DD],     g_outT_lo[LL * DD * DD];
__device__ __nv_bfloat16 g_ff1T_hi[LL * 4 * DD * DD], g_ff1T_lo[LL * 4 * DD * DD];
__device__ __nv_bfloat16 g_ff2T_hi[LL * 4 * DD * DD], g_ff2T_lo[LL * 4 * DD * DD];

// ---------------------------------------------------------------------------
// PTX helpers
// ---------------------------------------------------------------------------
__device__ __forceinline__ uint32_t smem_u32(const void* p) {
    uint32_t a;
    asm("{ .reg .u64 t; cvta.to.shared.u64 t, %1; cvt.u32.u64 %0, t; }"
        : "=r"(a) : "l"(p));
    return a;
}

__device__ __forceinline__ void cpa16(uint32_t dst, const void* src) {
    asm volatile("cp.async.cg.shared.global [%0], [%1], 16;" :: "r"(dst), "l"(src));
}
#define CPA_COMMIT() asm volatile("cp.async.commit_group;" ::: "memory")

__device__ __forceinline__ void ldsm4(uint32_t* r, uint32_t addr) {
    asm volatile("ldmatrix.sync.aligned.m8n8.x4.shared.b16 {%0,%1,%2,%3}, [%4];"
        : "=r"(r[0]), "=r"(r[1]), "=r"(r[2]), "=r"(r[3]) : "r"(addr));
}

__device__ __forceinline__ void mma_bf16(float* d, const uint32_t* a, const uint32_t* b) {
    asm volatile(
        "mma.sync.aligned.m16n8k16.row.col.f32.bf16.bf16.f32 "
        "{%0,%1,%2,%3}, {%4,%5,%6,%7}, {%8,%9}, {%0,%1,%2,%3};"
        : "+f"(d[0]), "+f"(d[1]), "+f"(d[2]), "+f"(d[3])
        : "r"(a[0]), "r"(a[1]), "r"(a[2]), "r"(a[3]), "r"(b[0]), "r"(b[1]));
}
__device__ __forceinline__ void mma_fp16(float* d, const uint32_t* a, const uint32_t* b) {
    asm volatile(
        "mma.sync.aligned.m16n8k16.row.col.f32.f16.f16.f32 "
        "{%0,%1,%2,%3}, {%4,%5,%6,%7}, {%8,%9}, {%0,%1,%2,%3};"
        : "+f"(d[0]), "+f"(d[1]), "+f"(d[2]), "+f"(d[3])
        : "r"(a[0]), "r"(a[1]), "r"(a[2]), "r"(a[3]), "r"(b[0]), "r"(b[1]));
}

__device__ __forceinline__ void split_bf(float v, __nv_bfloat16& hi, __nv_bfloat16& lo) {
    hi = __float2bfloat16(v);
    lo = __float2bfloat16(v - __bfloat162float(hi));
}
__device__ __forceinline__ uint32_t pack_bf2(float x, float y) {
    __nv_bfloat16 a = __float2bfloat16(x), b = __float2bfloat16(y);
    uint16_t ua = *(uint16_t*)&a, ub = *(uint16_t*)&b;
    return (uint32_t)ua | ((uint32_t)ub << 16);
}
__device__ __forceinline__ float bf_round(float x) {
    __nv_bfloat16 h = __float2bfloat16(x);
    return __bfloat162float(h);
}
__device__ __forceinline__ float gelu_exact(float v) {
    return 0.5f * v * (1.0f + erff(v * 0.70710678118654752f));
}

// ---------------------------------------------------------------------------
// Weight prep: transpose+split W[K,N] -> Thi/Tlo [N,K], batched over layers
// ---------------------------------------------------------------------------
__global__ __launch_bounds__(256) void wprep_T(
    const float* __restrict__ W, __nv_bfloat16* __restrict__ Thi,
    __nv_bfloat16* __restrict__ Tlo, int K, int N)
{
    __shared__ float tile[32][33];
    size_t lw = (size_t)blockIdx.z * K * N;
    const float* Wl = W + lw;
    __nv_bfloat16* Thl = Thi + lw;
    __nv_bfloat16* Tll = Tlo + lw;
    int n0 = blockIdx.x * 32, k0 = blockIdx.y * 32;
    int tx = threadIdx.x & 31, ty = threadIdx.x >> 5;
    #pragma unroll
    for (int i = ty; i < 32; i += 8)
        tile[i][tx] = Wl[(size_t)(k0 + i) * N + n0 + tx];
    __syncthreads();
    #pragma unroll
    for (int i = ty; i < 32; i += 8) {
        float v = tile[tx][i];
        size_t o = (size_t)(n0 + i) * K + k0 + tx;
        __nv_bfloat16 h, l; split_bf(v, h, l);
        Thl[o] = h; Tll[o] = l;
    }
}

// tok_emb -> fp16 (single rounding), for lm_head B operand
__global__ __launch_bounds__(256) void wprep_S16(
    const float4* __restrict__ W, __half* __restrict__ out, int n4)
{
    for (int i = blockIdx.x * blockDim.x + threadIdx.x; i < n4;
         i += gridDim.x * blockDim.x) {
        float4 v = W[i];
        ((__half2*)out)[i * 2    ] = __floats2half2_rn(v.x, v.y);
        ((__half2*)out)[i * 2 + 1] = __floats2half2_rn(v.z, v.w);
    }
}

// ---------------------------------------------------------------------------
// Embedding
// ---------------------------------------------------------------------------
__global__ __launch_bounds__(256) void embed_kernel(
    const int* __restrict__ idx, const float* __restrict__ tok_emb,
    const float* __restrict__ pos_emb, float* __restrict__ x)
{
    int tok = blockIdx.x;
    int id  = idx[tok];
    int p   = tok % TT;
    const float* te = tok_emb + (size_t)id * DD;
    const float* pe = pos_emb + (size_t)p  * DD;
    float* xr = x + (size_t)tok * DD;
    for (int d = threadIdx.x; d < DD; d += 256)
        xr[d] = te[d] + pe[d];
}

// ---------------------------------------------------------------------------
// LayerNorm with fused split-K reduction: if p0 != nullptr, x += p0 + p1
// (written back to xout if non-null) before the LN. F16 selects output dtype.
// ---------------------------------------------------------------------------
template<int F16>
__global__ __launch_bounds__(256) void ln_kernel(
    const float* __restrict__ x, const float* __restrict__ p0,
    const float* __restrict__ p1, const float* __restrict__ w,
    const float* __restrict__ b, void* __restrict__ ohi_v,
    void* __restrict__ olo_v, float* __restrict__ xout)
{
    int tok = blockIdx.x;
    int t   = threadIdx.x;
    size_t base = (size_t)tok * DD;
    const float* xr = x + base;
    float v0 = xr[t], v1 = xr[t + 256], v2 = xr[t + 512];
    if (p0) {
        v0 += p0[base + t      ] + p1[base + t      ];
        v1 += p0[base + t + 256] + p1[base + t + 256];
        v2 += p0[base + t + 512] + p1[base + t + 512];
        if (xout) {
            xout[base + t      ] = v0;
            xout[base + t + 256] = v1;
            xout[base + t + 512] = v2;
        }
    }
    float s  = v0 + v1 + v2;
    float s2 = v0*v0 + v1*v1 + v2*v2;
    #pragma unroll
    for (int off = 16; off; off >>= 1) {
        s  += __shfl_down_sync(0xffffffffu, s,  off);
        s2 += __shfl_down_sync(0xffffffffu, s2, off);
    }
    __shared__ float red[16];
    __shared__ float mean_s, rstd_s;
    int wid = t >> 5, lid = t & 31;
    if (lid == 0) { red[wid] = s; red[8 + wid] = s2; }
    __syncthreads();
    if (t == 0) {
        float S = 0.f, S2 = 0.f;
        #pragma unroll
        for (int i = 0; i < 8; i++) { S += red[i]; S2 += red[8 + i]; }
        float mean = S * (1.0f / DD);
        float var  = S2 * (1.0f / DD) - mean * mean;
        mean_s = mean;
        rstd_s = rsqrtf(var + 1e-5f);
    }
    __syncthreads();
    float mean = mean_s, rstd = rstd_s;
    #pragma unroll
    for (int q = 0; q < 3; q++) {
        int d = t + q * 256;
        float v = (q == 0 ? v0 : (q == 1 ? v1 : v2));
        float o = (v - mean) * rstd * w[d] + b[d];
        if (F16) {
            __half h = __float2half(o);
            __half l = __float2half(o - __half2float(h));
            ((__half*)ohi_v)[base + d] = h;
            ((__half*)olo_v)[base + d] = l;
        } else {
            __nv_bfloat16 h, l; split_bf(o, h, l);
            ((__nv_bfloat16*)ohi_v)[base + d] = h;
            ((__nv_bfloat16*)olo_v)[base + d] = l;
        }
    }
}

// ---------------------------------------------------------------------------
// Flash attention on HMMA, Q-tile = 128 rows (256 threads, 8 warps x 16 rows).
// K/V tiles 64 rows, double-buffered. 2 CTAs/SM. Heavy-tile-first ordering.
// ---------------------------------------------------------------------------
#define FP2 144
#define FMQ (128 * FP2)            // Q mat: 18432
#define FMK (64 * FP2)             // K/V mat: 9216
#define FLASH3_SMEM (2 * FMQ + 8 * FMK)   // 110592

__global__ __launch_bounds__(256, 2) void flash_hmma3(
    const __nv_bfloat16* __restrict__ q_hi, const __nv_bfloat16* __restrict__ q_lo,
    const __nv_bfloat16* __restrict__ k_hi, const __nv_bfloat16* __restrict__ k_lo,
    const __nv_bfloat16* __restrict__ vt_hi, const __nv_bfloat16* __restrict__ vt_lo,
    __nv_bfloat16* __restrict__ y_hi, __nv_bfloat16* __restrict__ y_lo)
{
    extern __shared__ char fsm[];
    const uint32_t sb  = smem_u32(fsm);
    const uint32_t sQh = sb, sQl = sb + FMQ;
    const uint32_t sKV = sb + 2 * FMQ;

    // heavy-first: largest qt (most k-tiles) launches earliest
    const int qt = gridDim.x - 1 - blockIdx.x;
    const int hh = blockIdx.y, b = blockIdx.z;
    const int t = threadIdx.x, lane = t & 31, w = t >> 5;
    const unsigned FULL = 0xffffffffu;
    const int NKT = 2 * qt + 2;    // k-tiles for this q-tile

    {
        const __nv_bfloat16* srcs[2] = {q_hi, q_lo};
        #pragma unroll
        for (int m2 = 0; m2 < 2; m2++) {
            #pragma unroll
            for (int j = 0; j < 4; j++) {
                int id = t * 4 + j;
                int r = id >> 3, c = id & 7;
                int tok = b * TT + qt * 128 + r;
                cpa16(sb + m2 * FMQ + r * FP2 + c * 16,
                      srcs[m2] + (size_t)tok * DD + hh * HDIM + c * 8);
            }
        }
        CPA_COMMIT();
    }
    auto load_kv = [&](int s, int kt) {
        const uint32_t base = sKV + s * (4 * FMK);
        #pragma unroll
        for (int j = 0; j < 2; j++) {
            int id = t * 2 + j;
            int r = id >> 3, c = id & 7;
            int tok = b * TT + kt * 64 + r;
            size_t koff = (size_t)tok * DD + hh * HDIM + c * 8;
            cpa16(base + 0 * FMK + r * FP2 + c * 16, k_hi + koff);
            cpa16(base + 1 * FMK + r * FP2 + c * 16, k_lo + koff);
            size_t voff = ((size_t)(b * HH + hh) * HDIM + r) * TT + kt * 64 + c * 8;
            cpa16(base + 2 * FMK + r * FP2 + c * 16, vt_hi + voff);
            cpa16(base + 3 * FMK + r * FP2 + c * 16, vt_lo + voff);
        }
        CPA_COMMIT();
    };

    float m[2] = {-1e30f, -1e30f}, l[2] = {0.f, 0.f};
    float O[8][4];
    #pragma unroll
    for (int nt = 0; nt < 8; nt++)
        #pragma unroll
        for (int e = 0; e < 4; e++) O[nt][e] = 0.f;

    const uint32_t aOff = (uint32_t)((w * 16 + (lane & 15)) * FP2 + (lane >> 4) * 16);
    const uint32_t bOff = (uint32_t)(((lane & 7) + (lane >> 4) * 8) * FP2
                                     + ((lane >> 3) & 1) * 16);

    load_kv(0, 0);

    for (int kt = 0; kt < NKT; kt++) {
        asm volatile("cp.async.wait_group 0;" ::: "memory");
        __syncthreads();
        if (kt + 1 < NKT) load_kv((kt + 1) & 1, kt + 1);

        const uint32_t bK = sKV + (kt & 1) * (4 * FMK);

        float S[8][4];
        #pragma unroll
        for (int nt = 0; nt < 8; nt++)
            #pragma unroll
            for (int e = 0; e < 4; e++) S[nt][e] = 0.f;

        #pragma unroll
        for (int kk = 0; kk < 4; kk++) {
            uint32_t qh[4], ql[4];
            ldsm4(qh, sQh + aOff + kk * 32);
            ldsm4(ql, sQl + aOff + kk * 32);
            #pragma unroll
            for (int np = 0; np < 4; np++) {
                uint32_t kh[4], kl[4];
                ldsm4(kh, bK + 0 * FMK + bOff + np * (16 * FP2) + kk * 32);
                ldsm4(kl, bK + 1 * FMK + bOff + np * (16 * FP2) + kk * 32);
                #pragma unroll
                for (int sub = 0; sub < 2; sub++)
                    mma_bf16(S[2 * np + sub], qh, &kh[sub * 2]);
                #pragma unroll
                for (int sub = 0; sub < 2; sub++)
                    mma_bf16(S[2 * np + sub], qh, &kl[sub * 2]);
                #pragma unroll
                for (int sub = 0; sub < 2; sub++)
                    mma_bf16(S[2 * np + sub], ql, &kh[sub * 2]);
            }
        }

        if (kt >= 2 * qt) {
            #pragma unroll
            for (int nt = 0; nt < 8; nt++)
                #pragma unroll
                for (int e = 0; e < 4; e++) {
                    int col = kt * 64 + nt * 8 + (lane & 3) * 2 + (e & 1);
                    int row = qt * 128 + w * 16 + (lane >> 2) + (e >> 1) * 8;
                    S[nt][e] = (col > row) ? -1e30f : S[nt][e] * 0.125f;
                }
        } else {
            #pragma unroll
            for (int nt = 0; nt < 8; nt++)
                #pragma unroll
                for (int e = 0; e < 4; e++) S[nt][e] *= 0.125f;
        }

        float a[2];
        #pragma unroll
        for (int h = 0; h < 2; h++) {
            float mx = -1e30f;
            #pragma unroll
            for (int nt = 0; nt < 8; nt++)
                mx = fmaxf(mx, fmaxf(S[nt][2 * h], S[nt][2 * h + 1]));
            mx = fmaxf(mx, __shfl_xor_sync(FULL, mx, 1));
            mx = fmaxf(mx, __shfl_xor_sync(FULL, mx, 2));
            float mn = fmaxf(m[h], mx);
            a[h] = __expf(m[h] - mn);
            float sum = 0.f;
            #pragma unroll
            for (int nt = 0; nt < 8; nt++) {
                float p0 = __expf(S[nt][2 * h    ] - mn);
                float p1 = __expf(S[nt][2 * h + 1] - mn);
                S[nt][2 * h] = p0; S[nt][2 * h + 1] = p1;
                sum += p0 + p1;
            }
            sum += __shfl_xor_sync(FULL, sum, 1);
            sum += __shfl_xor_sync(FULL, sum, 2);
            l[h] = l[h] * a[h] + sum;
            m[h] = mn;
        }
        #pragma unroll
        for (int nt = 0; nt < 8; nt++) {
            O[nt][0] *= a[0]; O[nt][1] *= a[0];
            O[nt][2] *= a[1]; O[nt][3] *= a[1];
        }

        #pragma unroll
        for (int kb = 0; kb < 4; kb++) {
            uint32_t pah[4], pal[4];
            {
                float x0 = S[2*kb][0], x1 = S[2*kb][1], x2 = S[2*kb][2], x3 = S[2*kb][3];
                float y0 = S[2*kb+1][0], y1 = S[2*kb+1][1], y2 = S[2*kb+1][2], y3 = S[2*kb+1][3];
                float hx0 = bf_round(x0), hx1 = bf_round(x1), hx2 = bf_round(x2), hx3 = bf_round(x3);
                float hy0 = bf_round(y0), hy1 = bf_round(y1), hy2 = bf_round(y2), hy3 = bf_round(y3);
                pah[0] = pack_bf2(hx0, hx1); pah[1] = pack_bf2(hx2, hx3);
                pah[2] = pack_bf2(hy0, hy1); pah[3] = pack_bf2(hy2, hy3);
                pal[0] = pack_bf2(x0 - hx0, x1 - hx1); pal[1] = pack_bf2(x2 - hx2, x3 - hx3);
                pal[2] = pack_bf2(y0 - hy0, y1 - hy1); pal[3] = pack_bf2(y2 - hy2, y3 - hy3);
            }
            #pragma unroll
            for (int np = 0; np < 4; np++) {
                uint32_t vh[4], vl[4];
                ldsm4(vh, bK + 2 * FMK + bOff + np * (16 * FP2) + kb * 32);
                ldsm4(vl, bK + 3 * FMK + bOff + np * (16 * FP2) + kb * 32);
                #pragma unroll
                for (int sub = 0; sub < 2; sub++)
                    mma_bf16(O[2 * np + sub], pah, &vh[sub * 2]);
                #pragma unroll
                for (int sub = 0; sub < 2; sub++)
                    mma_bf16(O[2 * np + sub], pah, &vl[sub * 2]);
                #pragma unroll
                for (int sub = 0; sub < 2; sub++)
                    mma_bf16(O[2 * np + sub], pal, &vh[sub * 2]);
            }
        }
    }

    float inv[2] = {1.0f / l[0], 1.0f / l[1]};
    #pragma unroll
    for (int nt = 0; nt < 8; nt++) {
        int col = nt * 8 + (lane & 3) * 2;
        #pragma unroll
        for (int h = 0; h < 2; h++) {
            int row = qt * 128 + w * 16 + (lane >> 2) + h * 8;
            int tok = b * TT + row;
            size_t base = (size_t)tok * DD + hh * HDIM + col;
            float v0 = O[nt][2 * h    ] * inv[h];
            float v1 = O[nt][2 * h + 1] * inv[h];
            float h0 = bf_round(v0), h1 = bf_round(v1);
            *(uint32_t*)((char*)y_hi + base * 2) = pack_bf2(h0, h1);
            *(uint32_t*)((char*)y_lo + base * 2) = pack_bf2(v0 - h0, v1 - h1);
        }
    }
}

// ---------------------------------------------------------------------------
// HMMA GEMM 64x128 tile (bf16 3-term split). 8 warps: 2(M) x 4(N). 2 CTAs/SM.
// EPI: 0 = split-K partial store (grid.y = 2*M/64; half 0->Cf0, half 1->Cf1);
//      2 = gelu->split; 3 = qkv split/route. Khalf = K-extent per CTA.
// ---------------------------------------------------------------------------
#define GPITCH 144
#define AMAT64 (64 * GPITCH)                 // 9216
#define BMAT64 (128 * GPITCH)                // 18432
#define STG64  (2 * AMAT64 + 2 * BMAT64)     // 55296
#define GEMM64_SMEM (2 * STG64)              // 110592

template<int EPI>
__global__ __launch_bounds__(256, 1) void gemm_mma64(
    const __nv_bfloat16* __restrict__ Ahi, const __nv_bfloat16* __restrict__ Alo,
    const __nv_bfloat16* __restrict__ Bhi, const __nv_bfloat16* __restrict__ Blo,
    float* __restrict__ Cf0, float* __restrict__ Cf1,
    __nv_bfloat16* __restrict__ Chi, __nv_bfloat16* __restrict__ Clo,
    __nv_bfloat16* __restrict__ Qh, __nv_bfloat16* __restrict__ Ql,
    __nv_bfloat16* __restrict__ Kh, __nv_bfloat16* __restrict__ Kl,
    __nv_bfloat16* __restrict__ Vth, __nv_bfloat16* __restrict__ Vtl,
    int M, int N, int K, int Khalf)
{
    extern __shared__ char smem[];
    const uint32_t sb = smem_u32(smem);
    const int t = threadIdx.x;

    const int mtiles = M >> 6;
    const int half   = blockIdx.y / mtiles;          // 0 except split-K upper
    const int bm     = (blockIdx.y % mtiles) * 64;
    const int bn     = blockIdx.x * 128;
    const int k0     = half * Khalf;
    Ahi += k0; Alo += k0; Bhi += k0; Blo += k0;
    const int NK = Khalf >> 6;
    const int lane = t & 31;
    const int w    = t >> 5;
    const int wm   = w & 1;
    const int wn   = w >> 1;

    const int rbase = t >> 3;
    const int cc    = t & 7;
    auto load_stage = [&](int s, int kt) {
        const int koff = kt * 64 + cc * 8;
        const uint32_t stg = sb + s * STG64;
        #pragma unroll
        for (int i = 0; i < 2; i++) {
            int r = rbase + 32 * i;
            cpa16(stg + r * GPITCH + cc * 16, Ahi + (size_t)(bm + r) * K + koff);
        }
        #pragma unroll
        for (int i = 0; i < 2; i++) {
            int r = rbase + 32 * i;
            cpa16(stg + AMAT64 + r * GPITCH + cc * 16, Alo + (size_t)(bm + r) * K + koff);
        }
        #pragma unroll
        for (int i = 0; i < 4; i++) {
            int r = rbase + 32 * i;
            cpa16(stg + 2 * AMAT64 + r * GPITCH + cc * 16, Bhi + (size_t)(bn + r) * K + koff);
        }
        #pragma unroll
        for (int i = 0; i < 4; i++) {
            int r = rbase + 32 * i;
            cpa16(stg + 2 * AMAT64 + BMAT64 + r * GPITCH + cc * 16,
                  Blo + (size_t)(bn + r) * K + koff);
        }
        CPA_COMMIT();
    };

    float acc[2][4][4];
    #pragma unroll
    for (int mt = 0; mt < 2; mt++)
        #pragma unroll
        for (int nt = 0; nt < 4; nt++)
            #pragma unroll
            for (int q = 0; q < 4; q++) acc[mt][nt][q] = 0.f;

    const uint32_t aOff = (uint32_t)((wm * 32 + (lane & 15)) * GPITCH + (lane >> 4) * 16);
    const uint32_t bOff = (uint32_t)((wn * 32 + (lane & 7) + (lane >> 4) * 8) * GPITCH
                                     + ((lane >> 3) & 1) * 16);

    load_stage(0, 0);

    for (int kt = 0; kt < NK; kt++) {
        const int s = kt & 1;
        asm volatile("cp.async.wait_group 0;" ::: "memory");
        __syncthreads();
        if (kt + 1 < NK) load_stage(s ^ 1, kt + 1);

        const uint32_t stg = sb + s * STG64;
        #pragma unroll
        for (int kk = 0; kk < 4; kk++) {
            uint32_t ah[2][4], al[2][4], bh[2][4], bl[2][4];
            #pragma unroll
            for (int mt = 0; mt < 2; mt++) {
                ldsm4(ah[mt], stg + aOff + mt * (16 * GPITCH) + kk * 32);
                ldsm4(al[mt], stg + AMAT64 + aOff + mt * (16 * GPITCH) + kk * 32);
            }
            #pragma unroll
            for (int np = 0; np < 2; np++) {
                ldsm4(bh[np], stg + 2 * AMAT64 + bOff + np * (16 * GPITCH) + kk * 32);
                ldsm4(bl[np], stg + 2 * AMAT64 + BMAT64 + bOff + np * (16 * GPITCH) + kk * 32);
            }
            #pragma unroll
            for (int mt = 0; mt < 2; mt++)
                #pragma unroll
                for (int nt = 0; nt < 4; nt++)
                    mma_bf16(acc[mt][nt], ah[mt], &bh[nt >> 1][(nt & 1) * 2]);
            #pragma unroll
            for (int mt = 0; mt < 2; mt++)
                #pragma unroll
                for (int nt = 0; nt < 4; nt++)
                    mma_bf16(acc[mt][nt], ah[mt], &bl[nt >> 1][(nt & 1) * 2]);
            #pragma unroll
            for (int mt = 0; mt < 2; mt++)
                #pragma unroll
                for (int nt = 0; nt < 4; nt++)
                    mma_bf16(acc[mt][nt], al[mt], &bh[nt >> 1][(nt & 1) * 2]);
        }
    }

    float* dst = half ? Cf1 : Cf0;
    #pragma unroll
    for (int mt = 0; mt < 2; mt++) {
        const int row0 = bm + wm * 32 + mt * 16 + (lane >> 2);
        #pragma unroll
        for (int nt = 0; nt < 4; nt++) {
            const int col = bn + wn * 32 + nt * 8 + (lane & 3) * 2;
            #pragma unroll
            for (int half2 = 0; half2 < 2; half2++) {
                const int row = row0 + half2 * 8;
                const float v0 = acc[mt][nt][half2 * 2 + 0];
                const float v1 = acc[mt][nt][half2 * 2 + 1];
                const size_t off = (size_t)row * N + col;
                if (EPI == 0) {
                    float2 v; v.x = v0; v.y = v1;
                    *(float2*)(dst + off) = v;
                } else if (EPI == 2) {
                    float g0 = gelu_exact(v0), g1 = gelu_exact(v1);
                    float h0 = bf_round(g0), h1 = bf_round(g1);
                    *(uint32_t*)((char*)Chi + off * 2) = pack_bf2(h0, h1);
                    *(uint32_t*)((char*)Clo + off * 2) = pack_bf2(g0 - h0, g1 - h1);
                } else {  // EPI == 3: qkv split + route
                    float h0 = bf_round(v0), h1 = bf_round(v1);
                    if (bn < DD) {
                        size_t o2 = ((size_t)row * DD + col) * 2;
                        *(uint32_t*)((char*)Qh + o2) = pack_bf2(h0, h1);
                        *(uint32_t*)((char*)Ql + o2) = pack_bf2(v0 - h0, v1 - h1);
                    } else if (bn < 2 * DD) {
                        size_t o2 = ((size_t)row * DD + (col - DD)) * 2;
                        *(uint32_t*)((char*)Kh + o2) = pack_bf2(h0, h1);
                        *(uint32_t*)((char*)Kl + o2) = pack_bf2(v0 - h0, v1 - h1);
                    } else {
                        int c  = col - 2 * DD;
                        int hq = c >> 6, hd = c & 63;
                        int bb2 = row >> 11, tt2 = row & 2047;
                        size_t a0 = ((size_t)(bb2 * HH + hq) * HDIM + hd) * TT + tt2;
                        __nv_bfloat16 hb0 = __float2bfloat16(h0);
                        __nv_bfloat16 hb1 = __float2bfloat16(h1);
                        __nv_bfloat16 lb0 = __float2bfloat16(v0 - h0);
                        __nv_bfloat16 lb1 = __float2bfloat16(v1 - h1);
                        Vth[a0]      = hb0; Vtl[a0]      = lb0;
                        Vth[a0 + TT] = hb1; Vtl[a0 + TT] = lb1;
                    }
                }
            }
        }
    }
}

// ---------------------------------------------------------------------------
// lm_head GEMM: fp16 2-term split, 64x128 tile, group swizzle. (R11 verified)
// ---------------------------------------------------------------------------
#define STG16_64 (2 * AMAT64 + BMAT64)        // 36864
#define GEMM16_SMEM (2 * STG16_64)            // 73728

__global__ __launch_bounds__(256, 1) void gemm_f16_64(
    const __half* __restrict__ Ahi, const __half* __restrict__ Alo,
    const __half* __restrict__ Bf, float* __restrict__ Cf,
    int M, int N, int K, int swz)
{
    extern __shared__ char smem[];
    const uint32_t sb = smem_u32(smem);
    const int t = threadIdx.x;

    int bx = blockIdx.x, by = blockIdx.y;
    if (swz > 0) {
        int L   = by * gridDim.x + bx;
        int grp = swz * gridDim.y;
        int g   = L / grp, r = L % grp;
        bx = g * swz + (r % swz);
        by = r / swz;
    }
    const int bm = by * 64;
    const int bn = bx * 128;
    const int NK = K >> 6;
    const int lane = t & 31;
    const int w    = t >> 5;
    const int wm   = w & 1;
    const int wn   = w >> 1;

    const int rbase = t >> 3;
    const int cc    = t & 7;
    auto load_stage = [&](int s, int kt) {
        const int koff = kt * 64 + cc * 8;
        const uint32_t stg = sb + s * STG16_64;
        #pragma unroll
        for (int i = 0; i < 2; i++) {
            int r = rbase + 32 * i;
            cpa16(stg + r * GPITCH + cc * 16, Ahi + (size_t)(bm + r) * K + koff);
        }
        #pragma unroll
        for (int i = 0; i < 2; i++) {
            int r = rbase + 32 * i;
            cpa16(stg + AMAT64 + r * GPITCH + cc * 16, Alo + (size_t)(bm + r) * K + koff);
        }
        #pragma unroll
        for (int i = 0; i < 4; i++) {
            int r = rbase + 32 * i;
            cpa16(stg + 2 * AMAT64 + r * GPITCH + cc * 16, Bf + (size_t)(bn + r) * K + koff);
        }
        CPA_COMMIT();
    };

    float acc[2][4][4];
    #pragma unroll
    for (int mt = 0; mt < 2; mt++)
        #pragma unroll
        for (int nt = 0; nt < 4; nt++)
            #pragma unroll
            for (int q = 0; q < 4; q++) acc[mt][nt][q] = 0.f;

    const uint32_t aOff = (uint32_t)((wm * 32 + (lane & 15)) * GPITCH + (lane >> 4) * 16);
    const uint32_t bOff = (uint32_t)((wn * 32 + (lane & 7) + (lane >> 4) * 8) * GPITCH
                                     + ((lane >> 3) & 1) * 16);

    load_stage(0, 0);

    for (int kt = 0; kt < NK; kt++) {
        const int s = kt & 1;
        asm volatile("cp.async.wait_group 0;" ::: "memory");
        __syncthreads();
        if (kt + 1 < NK) load_stage(s ^ 1, kt + 1);

        const uint32_t stg = sb + s * STG16_64;
        #pragma unroll
        for (int kk = 0; kk < 4; kk++) {
            uint32_t ah[2][4], al[2][4], bf[2][4];
            #pragma unroll
            for (int mt = 0; mt < 2; mt++) {
                ldsm4(ah[mt], stg + aOff + mt * (16 * GPITCH) + kk * 32);
                ldsm4(al[mt], stg + AMAT64 + aOff + mt * (16 * GPITCH) + kk * 32);
            }
            #pragma unroll
            for (int np = 0; np < 2; np++)
                ldsm4(bf[np], stg + 2 * AMAT64 + bOff + np * (16 * GPITCH) + kk * 32);
            #pragma unroll
            for (int mt = 0; mt < 2; mt++)
                #pragma unroll
                for (int nt = 0; nt < 4; nt++)
                    mma_fp16(acc[mt][nt], ah[mt], &bf[nt >> 1][(nt & 1) * 2]);
            #pragma unroll
            for (int mt = 0; mt < 2; mt++)
                #pragma unroll
                for (int nt = 0; nt < 4; nt++)
                    mma_fp16(acc[mt][nt], al[mt], &bf[nt >> 1][(nt & 1) * 2]);
        }
    }

    #pragma unroll
    for (int mt = 0; mt < 2; mt++) {
        const int row0 = bm + wm * 32 + mt * 16 + (lane >> 2);
        #pragma unroll
        for (int nt = 0; nt < 4; nt++) {
            const int col = bn + wn * 32 + nt * 8 + (lane & 3) * 2;
            #pragma unroll
            for (int half = 0; half < 2; half++) {
                const int row = row0 + half * 8;
                const size_t off = (size_t)row * N + col;
                float2 v;
                v.x = acc[mt][nt][half * 2 + 0];
                v.y = acc[mt][nt][half * 2 + 1];
                *(float2*)(Cf + off) = v;
            }
        }
    }
}

// ---------------------------------------------------------------------------
extern "C" void kernel_launch(void* const* d_in, const int* in_sizes, int n_in,
                              void* d_out, int out_size)
{
    const int*   idx     = (const int*)  d_in[0];
    const float* tok_emb = (const float*)d_in[1];
    const float* pos_emb = (const float*)d_in[2];
    const float* ln1_w   = (const float*)d_in[3];
    const float* ln1_b   = (const float*)d_in[4];
    const float* qkv_w   = (const float*)d_in[5];
    const float* out_w   = (const float*)d_in[6];
    const float* ln2_w   = (const float*)d_in[7];
    const float* ln2_b   = (const float*)d_in[8];
    const float* ff1_w   = (const float*)d_in[9];
    const float* ff2_w   = (const float*)d_in[10];
    const float* lnf_w   = (const float*)d_in[11];
    const float* lnf_b   = (const float*)d_in[12];
    float* out = (float*)d_out;

    float *x, *p0, *p1;
    __nv_bfloat16 *h_hi, *h_lo, *y_hi, *y_lo, *ff_hi, *ff_lo;
    __nv_bfloat16 *q_hi, *q_lo, *k_hi, *k_lo, *vt_hi, *vt_lo;
    __nv_bfloat16 *qkvT_hi, *qkvT_lo, *outT_hi, *outT_lo;
    __nv_bfloat16 *ff1T_hi, *ff1T_lo, *ff2T_hi, *ff2T_lo;
    __half *h16_hi, *h16_lo, *emb16;
    cudaGetSymbolAddress((void**)&x,       g_x);
    cudaGetSymbolAddress((void**)&p0,      g_p0);
    cudaGetSymbolAddress((void**)&p1,      g_p1);
    cudaGetSymbolAddress((void**)&h_hi,    g_h_hi);
    cudaGetSymbolAddress((void**)&h_lo,    g_h_lo);
    cudaGetSymbolAddress((void**)&y_hi,    g_y_hi);
    cudaGetSymbolAddress((void**)&y_lo,    g_y_lo);
    cudaGetSymbolAddress((void**)&ff_hi,   g_ff_hi);
    cudaGetSymbolAddress((void**)&ff_lo,   g_ff_lo);
    cudaGetSymbolAddress((void**)&q_hi,    g_q_hi);
    cudaGetSymbolAddress((void**)&q_lo,    g_q_lo);
    cudaGetSymbolAddress((void**)&k_hi,    g_k_hi);
    cudaGetSymbolAddress((void**)&k_lo,    g_k_lo);
    cudaGetSymbolAddress((void**)&vt_hi,   g_vt_hi);
    cudaGetSymbolAddress((void**)&vt_lo,   g_vt_lo);
    cudaGetSymbolAddress((void**)&qkvT_hi, g_qkvT_hi);
    cudaGetSymbolAddress((void**)&qkvT_lo, g_qkvT_lo);
    cudaGetSymbolAddress((void**)&outT_hi, g_outT_hi);
    cudaGetSymbolAddress((void**)&outT_lo, g_outT_lo);
    cudaGetSymbolAddress((void**)&ff1T_hi, g_ff1T_hi);
    cudaGetSymbolAddress((void**)&ff1T_lo, g_ff1T_lo);
    cudaGetSymbolAddress((void**)&ff2T_hi, g_ff2T_hi);
    cudaGetSymbolAddress((void**)&ff2T_lo, g_ff2T_lo);
    cudaGetSymbolAddress((void**)&h16_hi,  g_h16_hi);
    cudaGetSymbolAddress((void**)&h16_lo,  g_h16_lo);
    cudaGetSymbolAddress((void**)&emb16,   g_emb16);

    cudaFuncSetAttribute(flash_hmma3,
                         cudaFuncAttributeMaxDynamicSharedMemorySize, FLASH3_SMEM);
    cudaFuncSetAttribute(gemm_mma64<0>,
                         cudaFuncAttributeMaxDynamicSharedMemorySize, GEMM64_SMEM);
    cudaFuncSetAttribute(gemm_mma64<2>,
                         cudaFuncAttributeMaxDynamicSharedMemorySize, GEMM64_SMEM);
    cudaFuncSetAttribute(gemm_mma64<3>,
                         cudaFuncAttributeMaxDynamicSharedMemorySize, GEMM64_SMEM);
    cudaFuncSetAttribute(gemm_f16_64,
                         cudaFuncAttributeMaxDynamicSharedMemorySize, GEMM16_SMEM);

    // ---- weight prep (batched over layers) ----
    wprep_S16<<<8192, 256>>>((const float4*)tok_emb, emb16, VV * DD / 4);
    wprep_T<<<dim3(3*DD/32, DD/32, LL), 256>>>(qkv_w, qkvT_hi, qkvT_lo, DD, 3*DD);
    wprep_T<<<dim3(DD/32,   DD/32, LL), 256>>>(out_w, outT_hi, outT_lo, DD, DD);
    wprep_T<<<dim3(4*DD/32, DD/32, LL), 256>>>(ff1_w, ff1T_hi, ff1T_lo, DD, 4*DD);
    wprep_T<<<dim3(DD/32, 4*DD/32, LL), 256>>>(ff2_w, ff2T_hi, ff2T_lo, 4*DD, DD);

    embed_kernel<<<MM, 256>>>(idx, tok_emb, pos_emb, x);

    for (int l = 0; l < LL; l++) {
        // ln1: fused add of previous layer's ff2 partials (none for layer 0)
        ln_kernel<0><<<MM, 256>>>(x, (l == 0) ? nullptr : p0, p1,
                                  ln1_w + l*DD, ln1_b + l*DD, h_hi, h_lo, x);
        gemm_mma64<3><<<dim3(3*DD/128, MM/64), 256, GEMM64_SMEM>>>(
            h_hi, h_lo, qkvT_hi + (size_t)l*3*DD*DD, qkvT_lo + (size_t)l*3*DD*DD,
            nullptr, nullptr, nullptr, nullptr,
            q_hi, q_lo, k_hi, k_lo, vt_hi, vt_lo, MM, 3*DD, DD, DD);
        flash_hmma3<<<dim3(TT/128, HH, BB), 256, FLASH3_SMEM>>>(
            q_hi, q_lo, k_hi, k_lo, vt_hi, vt_lo, y_hi, y_lo);
        // out-proj: split-K=2 into partials
        gemm_mma64<0><<<dim3(DD/128, 2*MM/64), 256, GEMM64_SMEM>>>(
            y_hi, y_lo, outT_hi + (size_t)l*DD*DD, outT_lo + (size_t)l*DD*DD,
            p0, p1, nullptr, nullptr,
            nullptr, nullptr, nullptr, nullptr, nullptr, nullptr,
            MM, DD, DD, DD/2);
        // ln2: fused x += p0+p1
        ln_kernel<0><<<MM, 256>>>(x, p0, p1,
                                  ln2_w + l*DD, ln2_b + l*DD, h_hi, h_lo, x);
        gemm_mma64<2><<<dim3(4*DD/128, MM/64), 256, GEMM64_SMEM>>>(
            h_hi, h_lo, ff1T_hi + (size_t)l*4*DD*DD, ff1T_lo + (size_t)l*4*DD*DD,
            nullptr, nullptr, ff_hi, ff_lo,
            nullptr, nullptr, nullptr, nullptr, nullptr, nullptr,
            MM, 4*DD, DD, DD);
        // ff2: split-K=2 into partials (folded into next ln1 / lnf)
        gemm_mma64<0><<<dim3(DD/128, 2*MM/64), 256, GEMM64_SMEM>>>(
            ff_hi, ff_lo, ff2T_hi + (size_t)l*4*DD*DD, ff2T_lo + (size_t)l*4*DD*DD,
            p0, p1, nullptr, nullptr,
            nullptr, nullptr, nullptr, nullptr, nullptr, nullptr,
            MM, DD, 4*DD, 2*DD);
    }

    // lnf: fused x += p0+p1 from the last ff2 (no xout write needed)
    ln_kernel<1><<<MM, 256>>>(x, p0, p1, lnf_w, lnf_b, h16_hi, h16_lo, nullptr);
    gemm_f16_64<<<dim3(VV/128, MM/64), 256, GEMM16_SMEM>>>(
        h16_hi, h16_lo, emb16, out, MM, VV, DD, 25);
}

// round 16
// speedup vs baseline: 1.0568x; 1.0014x over previous
#include <cuda_runtime.h>
#include <cuda_bf16.h>
#include <cuda_fp16.h>
#include <math.h>
#include <stdint.h>

#define BB 2
#define TT 2048
#define LL 6
#define HH 12
#define DD 768
#define HDIM 64
#define VV 32000
#define MM (BB*TT)          // 4096 tokens

// ---------------------------------------------------------------------------
// Scratch (device globals; no allocation allowed)
// ---------------------------------------------------------------------------
__device__ float g_x  [MM * DD];            // residual stream (fp32)
__device__ float g_p0 [MM * DD];            // split-K partial 0 (fp32)
__device__ float g_p1 [MM * DD];            // split-K partial 1 (fp32)
__device__ __nv_bfloat16 g_h_hi[MM * DD],      g_h_lo[MM * DD];       // LN out split
__device__ __nv_bfloat16 g_y_hi[MM * DD],      g_y_lo[MM * DD];       // attn out split
__device__ __nv_bfloat16 g_ff_hi[MM * 4 * DD], g_ff_lo[MM * 4 * DD];  // gelu out split
// qkv split outputs (written by QKV GEMM epilogue)
__device__ __nv_bfloat16 g_q_hi[MM * DD],  g_q_lo[MM * DD];   // [tok][768]
__device__ __nv_bfloat16 g_k_hi[MM * DD],  g_k_lo[MM * DD];   // [tok][768]
__device__ __nv_bfloat16 g_vt_hi[MM * DD], g_vt_lo[MM * DD];  // [b,h][hd][tok]
// fp16 path for lm_head
__device__ __half g_h16_hi[MM * DD], g_h16_lo[MM * DD];
__device__ __half g_emb16[VV * DD];                            // [V][D] fp16
// transposed + split weights [N,K]
__device__ __nv_bfloat16 g_qkvT_hi[LL * 3 * DD * DD], g_qkvT_lo[LL * 3 * DD * DD];
__device__ __nv_bfloat16 g_outT_hi[LL * DD * DD],     g_outT_lo[LL * DD * DD];
__device__ __nv_bfloat16 g_ff1T_hi[LL * 4 * DD * DD], g_ff1T_lo[LL * 4 * DD * DD];
__device__ __nv_bfloat16 g_ff2T_hi[LL * 4 * DD * DD], g_ff2T_lo[LL * 4 * DD * DD];

// ---------------------------------------------------------------------------
// PTX helpers
// ---------------------------------------------------------------------------
__device__ __forceinline__ uint32_t smem_u32(const void* p) {
    uint32_t a;
    asm("{ .reg .u64 t; cvta.to.shared.u64 t, %1; cvt.u32.u64 %0, t; }"
        : "=r"(a) : "l"(p));
    return a;
}

__device__ __forceinline__ void cpa16(uint32_t dst, const void* src) {
    asm volatile("cp.async.cg.shared.global [%0], [%1], 16;" :: "r"(dst), "l"(src));
}
#define CPA_COMMIT() asm volatile("cp.async.commit_group;" ::: "memory")

__device__ __forceinline__ void ldsm4(uint32_t* r, uint32_t addr) {
    asm volatile("ldmatrix.sync.aligned.m8n8.x4.shared.b16 {%0,%1,%2,%3}, [%4];"
        : "=r"(r[0]), "=r"(r[1]), "=r"(r[2]), "=r"(r[3]) : "r"(addr));
}

__device__ __forceinline__ void mma_bf16(float* d, const uint32_t* a, const uint32_t* b) {
    asm volatile(
        "mma.sync.aligned.m16n8k16.row.col.f32.bf16.bf16.f32 "
        "{%0,%1,%2,%3}, {%4,%5,%6,%7}, {%8,%9}, {%0,%1,%2,%3};"
        : "+f"(d[0]), "+f"(d[1]), "+f"(d[2]), "+f"(d[3])
        : "r"(a[0]), "r"(a[1]), "r"(a[2]), "r"(a[3]), "r"(b[0]), "r"(b[1]));
}
__device__ __forceinline__ void mma_fp16(float* d, const uint32_t* a, const uint32_t* b) {
    asm volatile(
        "mma.sync.aligned.m16n8k16.row.col.f32.f16.f16.f32 "
        "{%0,%1,%2,%3}, {%4,%5,%6,%7}, {%8,%9}, {%0,%1,%2,%3};"
        : "+f"(d[0]), "+f"(d[1]), "+f"(d[2]), "+f"(d[3])
        : "r"(a[0]), "r"(a[1]), "r"(a[2]), "r"(a[3]), "r"(b[0]), "r"(b[1]));
}

__device__ __forceinline__ void split_bf(float v, __nv_bfloat16& hi, __nv_bfloat16& lo) {
    hi = __float2bfloat16(v);
    lo = __float2bfloat16(v - __bfloat162float(hi));
}
__device__ __forceinline__ uint32_t pack_bf2(float x, float y) {
    __nv_bfloat16 a = __float2bfloat16(x), b = __float2bfloat16(y);
    uint16_t ua = *(uint16_t*)&a, ub = *(uint16_t*)&b;
    return (uint32_t)ua | ((uint32_t)ub << 16);
}
__device__ __forceinline__ float bf_round(float x) {
    __nv_bfloat16 h = __float2bfloat16(x);
    return __bfloat162float(h);
}
__device__ __forceinline__ float gelu_exact(float v) {
    return 0.5f * v * (1.0f + erff(v * 0.70710678118654752f));
}

// ---------------------------------------------------------------------------
// Weight prep: transpose+split W[K,N] -> Thi/Tlo [N,K], batched over layers
// ---------------------------------------------------------------------------
__global__ __launch_bounds__(256) void wprep_T(
    const float* __restrict__ W, __nv_bfloat16* __restrict__ Thi,
    __nv_bfloat16* __restrict__ Tlo, int K, int N)
{
    __shared__ float tile[32][33];
    size_t lw = (size_t)blockIdx.z * K * N;
    const float* Wl = W + lw;
    __nv_bfloat16* Thl = Thi + lw;
    __nv_bfloat16* Tll = Tlo + lw;
    int n0 = blockIdx.x * 32, k0 = blockIdx.y * 32;
    int tx = threadIdx.x & 31, ty = threadIdx.x >> 5;
    #pragma unroll
    for (int i = ty; i < 32; i += 8)
        tile[i][tx] = Wl[(size_t)(k0 + i) * N + n0 + tx];
    __syncthreads();
    #pragma unroll
    for (int i = ty; i < 32; i += 8) {
        float v = tile[tx][i];
        size_t o = (size_t)(n0 + i) * K + k0 + tx;
        __nv_bfloat16 h, l; split_bf(v, h, l);
        Thl[o] = h; Tll[o] = l;
    }
}

// tok_emb -> fp16 (single rounding), for lm_head B operand
__global__ __launch_bounds__(256) void wprep_S16(
    const float4* __restrict__ W, __half* __restrict__ out, int n4)
{
    for (int i = blockIdx.x * blockDim.x + threadIdx.x; i < n4;
         i += gridDim.x * blockDim.x) {
        float4 v = W[i];
        ((__half2*)out)[i * 2    ] = __floats2half2_rn(v.x, v.y);
        ((__half2*)out)[i * 2 + 1] = __floats2half2_rn(v.z, v.w);
    }
}

// ---------------------------------------------------------------------------
// Embedding
// ---------------------------------------------------------------------------
__global__ __launch_bounds__(256) void embed_kernel(
    const int* __restrict__ idx, const float* __restrict__ tok_emb,
    const float* __restrict__ pos_emb, float* __restrict__ x)
{
    int tok = blockIdx.x;
    int id  = idx[tok];
    int p   = tok % TT;
    const float* te = tok_emb + (size_t)id * DD;
    const float* pe = pos_emb + (size_t)p  * DD;
    float* xr = x + (size_t)tok * DD;
    for (int d = threadIdx.x; d < DD; d += 256)
        xr[d] = te[d] + pe[d];
}

// ---------------------------------------------------------------------------
// LayerNorm with fused split-K reduction: if p0 != nullptr, x += p0 + p1
// (written back to xout if non-null) before the LN. F16 selects output dtype.
// ---------------------------------------------------------------------------
template<int F16>
__global__ __launch_bounds__(256) void ln_kernel(
    const float* __restrict__ x, const float* __restrict__ p0,
    const float* __restrict__ p1, const float* __restrict__ w,
    const float* __restrict__ b, void* __restrict__ ohi_v,
    void* __restrict__ olo_v, float* __restrict__ xout)
{
    int tok = blockIdx.x;
    int t   = threadIdx.x;
    size_t base = (size_t)tok * DD;
    const float* xr = x + base;
    float v0 = xr[t], v1 = xr[t + 256], v2 = xr[t + 512];
    if (p0) {
        v0 += p0[base + t      ] + p1[base + t      ];
        v1 += p0[base + t + 256] + p1[base + t + 256];
        v2 += p0[base + t + 512] + p1[base + t + 512];
        if (xout) {
            xout[base + t      ] = v0;
            xout[base + t + 256] = v1;
            xout[base + t + 512] = v2;
        }
    }
    float s  = v0 + v1 + v2;
    float s2 = v0*v0 + v1*v1 + v2*v2;
    #pragma unroll
    for (int off = 16; off; off >>= 1) {
        s  += __shfl_down_sync(0xffffffffu, s,  off);
        s2 += __shfl_down_sync(0xffffffffu, s2, off);
    }
    __shared__ float red[16];
    __shared__ float mean_s, rstd_s;
    int wid = t >> 5, lid = t & 31;
    if (lid == 0) { red[wid] = s; red[8 + wid] = s2; }
    __syncthreads();
    if (t == 0) {
        float S = 0.f, S2 = 0.f;
        #pragma unroll
        for (int i = 0; i < 8; i++) { S += red[i]; S2 += red[8 + i]; }
        float mean = S * (1.0f / DD);
        float var  = S2 * (1.0f / DD) - mean * mean;
        mean_s = mean;
        rstd_s = rsqrtf(var + 1e-5f);
    }
    __syncthreads();
    float mean = mean_s, rstd = rstd_s;
    #pragma unroll
    for (int q = 0; q < 3; q++) {
        int d = t + q * 256;
        float v = (q == 0 ? v0 : (q == 1 ? v1 : v2));
        float o = (v - mean) * rstd * w[d] + b[d];
        if (F16) {
            __half h = __float2half(o);
            __half l = __float2half(o - __half2float(h));
            ((__half*)ohi_v)[base + d] = h;
            ((__half*)olo_v)[base + d] = l;
        } else {
            __nv_bfloat16 h, l; split_bf(o, h, l);
            ((__nv_bfloat16*)ohi_v)[base + d] = h;
            ((__nv_bfloat16*)olo_v)[base + d] = l;
        }
    }
}

// ---------------------------------------------------------------------------
// Flash attention on HMMA, Q-tile = 128 rows (256 threads, 8 warps x 16 rows).
// K/V tiles 64 rows, double-buffered. 2 CTAs/SM. Heavy-tile-first ordering.
// ---------------------------------------------------------------------------
#define FP2 144
#define FMQ (128 * FP2)            // Q mat: 18432
#define FMK (64 * FP2)             // K/V mat: 9216
#define FLASH3_SMEM (2 * FMQ + 8 * FMK)   // 110592

__global__ __launch_bounds__(256, 2) void flash_hmma3(
    const __nv_bfloat16* __restrict__ q_hi, const __nv_bfloat16* __restrict__ q_lo,
    const __nv_bfloat16* __restrict__ k_hi, const __nv_bfloat16* __restrict__ k_lo,
    const __nv_bfloat16* __restrict__ vt_hi, const __nv_bfloat16* __restrict__ vt_lo,
    __nv_bfloat16* __restrict__ y_hi, __nv_bfloat16* __restrict__ y_lo)
{
    extern __shared__ char fsm[];
    const uint32_t sb  = smem_u32(fsm);
    const uint32_t sQh = sb, sQl = sb + FMQ;
    const uint32_t sKV = sb + 2 * FMQ;

    // heavy-first: largest qt (most k-tiles) launches earliest
    const int qt = gridDim.x - 1 - blockIdx.x;
    const int hh = blockIdx.y, b = blockIdx.z;
    const int t = threadIdx.x, lane = t & 31, w = t >> 5;
    const unsigned FULL = 0xffffffffu;
    const int NKT = 2 * qt + 2;    // k-tiles for this q-tile

    {
        const __nv_bfloat16* srcs[2] = {q_hi, q_lo};
        #pragma unroll
        for (int m2 = 0; m2 < 2; m2++) {
            #pragma unroll
            for (int j = 0; j < 4; j++) {
                int id = t * 4 + j;
                int r = id >> 3, c = id & 7;
                int tok = b * TT + qt * 128 + r;
                cpa16(sb + m2 * FMQ + r * FP2 + c * 16,
                      srcs[m2] + (size_t)tok * DD + hh * HDIM + c * 8);
            }
        }
        CPA_COMMIT();
    }
    auto load_kv = [&](int s, int kt) {
        const uint32_t base = sKV + s * (4 * FMK);
        #pragma unroll
        for (int j = 0; j < 2; j++) {
            int id = t * 2 + j;
            int r = id >> 3, c = id & 7;
            int tok = b * TT + kt * 64 + r;
            size_t koff = (size_t)tok * DD + hh * HDIM + c * 8;
            cpa16(base + 0 * FMK + r * FP2 + c * 16, k_hi + koff);
            cpa16(base + 1 * FMK + r * FP2 + c * 16, k_lo + koff);
            size_t voff = ((size_t)(b * HH + hh) * HDIM + r) * TT + kt * 64 + c * 8;
            cpa16(base + 2 * FMK + r * FP2 + c * 16, vt_hi + voff);
            cpa16(base + 3 * FMK + r * FP2 + c * 16, vt_lo + voff);
        }
        CPA_COMMIT();
    };

    float m[2] = {-1e30f, -1e30f}, l[2] = {0.f, 0.f};
    float O[8][4];
    #pragma unroll
    for (int nt = 0; nt < 8; nt++)
        #pragma unroll
        for (int e = 0; e < 4; e++) O[nt][e] = 0.f;

    const uint32_t aOff = (uint32_t)((w * 16 + (lane & 15)) * FP2 + (lane >> 4) * 16);
    const uint32_t bOff = (uint32_t)(((lane & 7) + (lane >> 4) * 8) * FP2
                                     + ((lane >> 3) & 1) * 16);

    load_kv(0, 0);

    for (int kt = 0; kt < NKT; kt++) {
        asm volatile("cp.async.wait_group 0;" ::: "memory");
        __syncthreads();
        if (kt + 1 < NKT) load_kv((kt + 1) & 1, kt + 1);

        const uint32_t bK = sKV + (kt & 1) * (4 * FMK);

        float S[8][4];
        #pragma unroll
        for (int nt = 0; nt < 8; nt++)
            #pragma unroll
            for (int e = 0; e < 4; e++) S[nt][e] = 0.f;

        #pragma unroll
        for (int kk = 0; kk < 4; kk++) {
            uint32_t qh[4], ql[4];
            ldsm4(qh, sQh + aOff + kk * 32);
            ldsm4(ql, sQl + aOff + kk * 32);
            #pragma unroll
            for (int np = 0; np < 4; np++) {
                uint32_t kh[4], kl[4];
                ldsm4(kh, bK + 0 * FMK + bOff + np * (16 * FP2) + kk * 32);
                ldsm4(kl, bK + 1 * FMK + bOff + np * (16 * FP2) + kk * 32);
                #pragma unroll
                for (int sub = 0; sub < 2; sub++)
                    mma_bf16(S[2 * np + sub], qh, &kh[sub * 2]);
                #pragma unroll
                for (int sub = 0; sub < 2; sub++)
                    mma_bf16(S[2 * np + sub], qh, &kl[sub * 2]);
                #pragma unroll
                for (int sub = 0; sub < 2; sub++)
                    mma_bf16(S[2 * np + sub], ql, &kh[sub * 2]);
            }
        }

        if (kt >= 2 * qt) {
            #pragma unroll
            for (int nt = 0; nt < 8; nt++)
                #pragma unroll
                for (int e = 0; e < 4; e++) {
                    int col = kt * 64 + nt * 8 + (lane & 3) * 2 + (e & 1);
                    int row = qt * 128 + w * 16 + (lane >> 2) + (e >> 1) * 8;
                    S[nt][e] = (col > row) ? -1e30f : S[nt][e] * 0.125f;
                }
        } else {
            #pragma unroll
            for (int nt = 0; nt < 8; nt++)
                #pragma unroll
                for (int e = 0; e < 4; e++) S[nt][e] *= 0.125f;
        }

        float a[2];
        #pragma unroll
        for (int h = 0; h < 2; h++) {
            float mx = -1e30f;
            #pragma unroll
            for (int nt = 0; nt < 8; nt++)
                mx = fmaxf(mx, fmaxf(S[nt][2 * h], S[nt][2 * h + 1]));
            mx = fmaxf(mx, __shfl_xor_sync(FULL, mx, 1));
            mx = fmaxf(mx, __shfl_xor_sync(FULL, mx, 2));
            float mn = fmaxf(m[h], mx);
            a[h] = __expf(m[h] - mn);
            float sum = 0.f;
            #pragma unroll
            for (int nt = 0; nt < 8; nt++) {
                float p0 = __expf(S[nt][2 * h    ] - mn);
                float p1 = __expf(S[nt][2 * h + 1] - mn);
                S[nt][2 * h] = p0; S[nt][2 * h + 1] = p1;
                sum += p0 + p1;
            }
            sum += __shfl_xor_sync(FULL, sum, 1);
            sum += __shfl_xor_sync(FULL, sum, 2);
            l[h] = l[h] * a[h] + sum;
            m[h] = mn;
        }
        #pragma unroll
        for (int nt = 0; nt < 8; nt++) {
            O[nt][0] *= a[0]; O[nt][1] *= a[0];
            O[nt][2] *= a[1]; O[nt][3] *= a[1];
        }

        #pragma unroll
        for (int kb = 0; kb < 4; kb++) {
            uint32_t pah[4], pal[4];
            {
                float x0 = S[2*kb][0], x1 = S[2*kb][1], x2 = S[2*kb][2], x3 = S[2*kb][3];
                float y0 = S[2*kb+1][0], y1 = S[2*kb+1][1], y2 = S[2*kb+1][2], y3 = S[2*kb+1][3];
                float hx0 = bf_round(x0), hx1 = bf_round(x1), hx2 = bf_round(x2), hx3 = bf_round(x3);
                float hy0 = bf_round(y0), hy1 = bf_round(y1), hy2 = bf_round(y2), hy3 = bf_round(y3);
                pah[0] = pack_bf2(hx0, hx1); pah[1] = pack_bf2(hx2, hx3);
                pah[2] = pack_bf2(hy0, hy1); pah[3] = pack_bf2(hy2, hy3);
                pal[0] = pack_bf2(x0 - hx0, x1 - hx1); pal[1] = pack_bf2(x2 - hx2, x3 - hx3);
                pal[2] = pack_bf2(y0 - hy0, y1 - hy1); pal[3] = pack_bf2(y2 - hy2, y3 - hy3);
            }
            #pragma unroll
            for (int np = 0; np < 4; np++) {
                uint32_t vh[4], vl[4];
                ldsm4(vh, bK + 2 * FMK + bOff + np * (16 * FP2) + kb * 32);
                ldsm4(vl, bK + 3 * FMK + bOff + np * (16 * FP2) + kb * 32);
                #pragma unroll
                for (int sub = 0; sub < 2; sub++)
                    mma_bf16(O[2 * np + sub], pah, &vh[sub * 2]);
                #pragma unroll
                for (int sub = 0; sub < 2; sub++)
                    mma_bf16(O[2 * np + sub], pah, &vl[sub * 2]);
                #pragma unroll
                for (int sub = 0; sub < 2; sub++)
                    mma_bf16(O[2 * np + sub], pal, &vh[sub * 2]);
            }
        }
    }

    float inv[2] = {1.0f / l[0], 1.0f / l[1]};
    #pragma unroll
    for (int nt = 0; nt < 8; nt++) {
        int col = nt * 8 + (lane & 3) * 2;
        #pragma unroll
        for (int h = 0; h < 2; h++) {
            int row = qt * 128 + w * 16 + (lane >> 2) + h * 8;
            int tok = b * TT + row;
            size_t base = (size_t)tok * DD + hh * HDIM + col;
            float v0 = O[nt][2 * h    ] * inv[h];
            float v1 = O[nt][2 * h + 1] * inv[h];
            float h0 = bf_round(v0), h1 = bf_round(v1);
            *(uint32_t*)((char*)y_hi + base * 2) = pack_bf2(h0, h1);
            *(uint32_t*)((char*)y_lo + base * 2) = pack_bf2(v0 - h0, v1 - h1);
        }
    }
}

// ---------------------------------------------------------------------------
// HMMA GEMM 64x128 tile (bf16 3-term split). 8 warps: 2(M) x 4(N). 2 CTAs/SM.
// EPI: 0 = split-K partial store (grid.y = 2*M/64; half 0->Cf0, half 1->Cf1);
//      2 = gelu->split; 3 = qkv split/route (V region: smem-staged transpose).
// ---------------------------------------------------------------------------
#define GPITCH 144
#define AMAT64 (64 * GPITCH)                 // 9216
#define BMAT64 (128 * GPITCH)                // 18432
#define STG64  (2 * AMAT64 + 2 * BMAT64)     // 55296
#define GEMM64_SMEM (2 * STG64)              // 110592
#define VSP 144                              // V staging pitch (16B aligned)

template<int EPI>
__global__ __launch_bounds__(256, 1) void gemm_mma64(
    const __nv_bfloat16* __restrict__ Ahi, const __nv_bfloat16* __restrict__ Alo,
    const __nv_bfloat16* __restrict__ Bhi, const __nv_bfloat16* __restrict__ Blo,
    float* __restrict__ Cf0, float* __restrict__ Cf1,
    __nv_bfloat16* __restrict__ Chi, __nv_bfloat16* __restrict__ Clo,
    __nv_bfloat16* __restrict__ Qh, __nv_bfloat16* __restrict__ Ql,
    __nv_bfloat16* __restrict__ Kh, __nv_bfloat16* __restrict__ Kl,
    __nv_bfloat16* __restrict__ Vth, __nv_bfloat16* __restrict__ Vtl,
    int M, int N, int K, int Khalf)
{
    extern __shared__ char smem[];
    const uint32_t sb = smem_u32(smem);
    const int t = threadIdx.x;

    const int mtiles = M >> 6;
    const int half   = blockIdx.y / mtiles;          // 0 except split-K upper
    const int bm     = (blockIdx.y % mtiles) * 64;
    const int bn     = blockIdx.x * 128;
    const int k0     = half * Khalf;
    Ahi += k0; Alo += k0; Bhi += k0; Blo += k0;
    const int NK = Khalf >> 6;
    const int lane = t & 31;
    const int w    = t >> 5;
    const int wm   = w & 1;
    const int wn   = w >> 1;

    const int rbase = t >> 3;
    const int cc    = t & 7;
    auto load_stage = [&](int s, int kt) {
        const int koff = kt * 64 + cc * 8;
        const uint32_t stg = sb + s * STG64;
        #pragma unroll
        for (int i = 0; i < 2; i++) {
            int r = rbase + 32 * i;
            cpa16(stg + r * GPITCH + cc * 16, Ahi + (size_t)(bm + r) * K + koff);
        }
        #pragma unroll
        for (int i = 0; i < 2; i++) {
            int r = rbase + 32 * i;
            cpa16(stg + AMAT64 + r * GPITCH + cc * 16, Alo + (size_t)(bm + r) * K + koff);
        }
        #pragma unroll
        for (int i = 0; i < 4; i++) {
            int r = rbase + 32 * i;
            cpa16(stg + 2 * AMAT64 + r * GPITCH + cc * 16, Bhi + (size_t)(bn + r) * K + koff);
        }
        #pragma unroll
        for (int i = 0; i < 4; i++) {
            int r = rbase + 32 * i;
            cpa16(stg + 2 * AMAT64 + BMAT64 + r * GPITCH + cc * 16,
                  Blo + (size_t)(bn + r) * K + koff);
        }
        CPA_COMMIT();
    };

    float acc[2][4][4];
    #pragma unroll
    for (int mt = 0; mt < 2; mt++)
        #pragma unroll
        for (int nt = 0; nt < 4; nt++)
            #pragma unroll
            for (int q = 0; q < 4; q++) acc[mt][nt][q] = 0.f;

    const uint32_t aOff = (uint32_t)((wm * 32 + (lane & 15)) * GPITCH + (lane >> 4) * 16);
    const uint32_t bOff = (uint32_t)((wn * 32 + (lane & 7) + (lane >> 4) * 8) * GPITCH
                                     + ((lane >> 3) & 1) * 16);

    load_stage(0, 0);

    for (int kt = 0; kt < NK; kt++) {
        const int s = kt & 1;
        asm volatile("cp.async.wait_group 0;" ::: "memory");
        __syncthreads();
        if (kt + 1 < NK) load_stage(s ^ 1, kt + 1);

        const uint32_t stg = sb + s * STG64;
        #pragma unroll
        for (int kk = 0; kk < 4; kk++) {
            uint32_t ah[2][4], al[2][4], bh[2][4], bl[2][4];
            #pragma unroll
            for (int mt = 0; mt < 2; mt++) {
                ldsm4(ah[mt], stg + aOff + mt * (16 * GPITCH) + kk * 32);
                ldsm4(al[mt], stg + AMAT64 + aOff + mt * (16 * GPITCH) + kk * 32);
            }
            #pragma unroll
            for (int np = 0; np < 2; np++) {
                ldsm4(bh[np], stg + 2 * AMAT64 + bOff + np * (16 * GPITCH) + kk * 32);
                ldsm4(bl[np], stg + 2 * AMAT64 + BMAT64 + bOff + np * (16 * GPITCH) + kk * 32);
            }
            #pragma unroll
            for (int mt = 0; mt < 2; mt++)
                #pragma unroll
                for (int nt = 0; nt < 4; nt++)
                    mma_bf16(acc[mt][nt], ah[mt], &bh[nt >> 1][(nt & 1) * 2]);
            #pragma unroll
            for (int mt = 0; mt < 2; mt++)
                #pragma unroll
                for (int nt = 0; nt < 4; nt++)
                    mma_bf16(acc[mt][nt], ah[mt], &bl[nt >> 1][(nt & 1) * 2]);
            #pragma unroll
            for (int mt = 0; mt < 2; mt++)
                #pragma unroll
                for (int nt = 0; nt < 4; nt++)
                    mma_bf16(acc[mt][nt], al[mt], &bh[nt >> 1][(nt & 1) * 2]);
        }
    }

    if (EPI == 3 && bn >= 2 * DD) {
        // ---- V region: stage transposed tile in smem, coalesced stores ----
        __syncthreads();   // all warps done reading stage smem
        #pragma unroll
        for (int mt = 0; mt < 2; mt++) {
            const int row0 = wm * 32 + mt * 16 + (lane >> 2);
            #pragma unroll
            for (int nt = 0; nt < 4; nt++) {
                const int cl = wn * 32 + nt * 8 + (lane & 3) * 2;
                #pragma unroll
                for (int h2 = 0; h2 < 2; h2++) {
                    const int row = row0 + h2 * 8;
                    float v0 = acc[mt][nt][h2 * 2 + 0];
                    float v1 = acc[mt][nt][h2 * 2 + 1];
                    float h0 = bf_round(v0), h1 = bf_round(v1);
                    *(__nv_bfloat16*)(smem + cl * VSP + row * 2) = __float2bfloat16(h0);
                    *(__nv_bfloat16*)(smem + (cl + 1) * VSP + row * 2) = __float2bfloat16(h1);
                    *(__nv_bfloat16*)(smem + 128 * VSP + cl * VSP + row * 2) =
                        __float2bfloat16(v0 - h0);
                    *(__nv_bfloat16*)(smem + 128 * VSP + (cl + 1) * VSP + row * 2) =
                        __float2bfloat16(v1 - h1);
                }
            }
        }
        __syncthreads();
        const int cbase = bn - 2 * DD;
        const int bb2 = bm / TT, tt0 = bm % TT;
        #pragma unroll
        for (int j = 0; j < 4; j++) {
            int id = t * 4 + j;          // 0..1023
            int c = id >> 3, part = id & 7;
            int gc = cbase + c;
            int hq = gc >> 6, hd = gc & 63;
            size_t a0 = ((size_t)(bb2 * HH + hq) * HDIM + hd) * TT + tt0 + part * 8;
            uint4 vhi = *(uint4*)(smem + c * VSP + part * 16);
            uint4 vlo = *(uint4*)(smem + 128 * VSP + c * VSP + part * 16);
            *(uint4*)((char*)Vth + a0 * 2) = vhi;
            *(uint4*)((char*)Vtl + a0 * 2) = vlo;
        }
        return;
    }

    float* dst = half ? Cf1 : Cf0;
    #pragma unroll
    for (int mt = 0; mt < 2; mt++) {
        const int row0 = bm + wm * 32 + mt * 16 + (lane >> 2);
        #pragma unroll
        for (int nt = 0; nt < 4; nt++) {
            const int col = bn + wn * 32 + nt * 8 + (lane & 3) * 2;
            #pragma unroll
            for (int half2 = 0; half2 < 2; half2++) {
                const int row = row0 + half2 * 8;
                const float v0 = acc[mt][nt][half2 * 2 + 0];
                const float v1 = acc[mt][nt][half2 * 2 + 1];
                const size_t off = (size_t)row * N + col;
                if (EPI == 0) {
                    float2 v; v.x = v0; v.y = v1;
                    *(float2*)(dst + off) = v;
                } else if (EPI == 2) {
                    float g0 = gelu_exact(v0), g1 = gelu_exact(v1);
                    float h0 = bf_round(g0), h1 = bf_round(g1);
                    *(uint32_t*)((char*)Chi + off * 2) = pack_bf2(h0, h1);
                    *(uint32_t*)((char*)Clo + off * 2) = pack_bf2(g0 - h0, g1 - h1);
                } else {  // EPI == 3: Q/K regions
                    float h0 = bf_round(v0), h1 = bf_round(v1);
                    if (bn < DD) {
                        size_t o2 = ((size_t)row * DD + col) * 2;
                        *(uint32_t*)((char*)Qh + o2) = pack_bf2(h0, h1);
                        *(uint32_t*)((char*)Ql + o2) = pack_bf2(v0 - h0, v1 - h1);
                    } else {
                        size_t o2 = ((size_t)row * DD + (col - DD)) * 2;
                        *(uint32_t*)((char*)Kh + o2) = pack_bf2(h0, h1);
                        *(uint32_t*)((char*)Kl + o2) = pack_bf2(v0 - h0, v1 - h1);
                    }
                }
            }
        }
    }
}

// ---------------------------------------------------------------------------
// lm_head GEMM: fp16 2-term split, 64x128 tile, group swizzle.
// ---------------------------------------------------------------------------
#define STG16_64 (2 * AMAT64 + BMAT64)        // 36864
#define GEMM16_SMEM (2 * STG16_64)            // 73728

__global__ __launch_bounds__(256, 2) void gemm_f16_64(
    const __half* __restrict__ Ahi, const __half* __restrict__ Alo,
    const __half* __restrict__ Bf, float* __restrict__ Cf,
    int M, int N, int K, int swz)
{
    extern __shared__ char smem[];
    const uint32_t sb = smem_u32(smem);
    const int t = threadIdx.x;

    int bx = blockIdx.x, by = blockIdx.y;
    if (swz > 0) {
        int L   = by * gridDim.x + bx;
        int grp = swz * gridDim.y;
        int g   = L / grp, r = L % grp;
        bx = g * swz + (r % swz);
        by = r / swz;
    }
    const int bm = by * 64;
    const int bn = bx * 128;
    const int NK = K >> 6;
    const int lane = t & 31;
    const int w    = t >> 5;
    const int wm   = w & 1;
    const int wn   = w >> 1;

    const int rbase = t >> 3;
    const int cc    = t & 7;
    auto load_stage = [&](int s, int kt) {
        const int koff = kt * 64 + cc * 8;
        const uint32_t stg = sb + s * STG16_64;
        #pragma unroll
        for (int i = 0; i < 2; i++) {
            int r = rbase + 32 * i;
            cpa16(stg + r * GPITCH + cc * 16, Ahi + (size_t)(bm + r) * K + koff);
        }
        #pragma unroll
        for (int i = 0; i < 2; i++) {
            int r = rbase + 32 * i;
            cpa16(stg + AMAT64 + r * GPITCH + cc * 16, Alo + (size_t)(bm + r) * K + koff);
        }
        #pragma unroll
        for (int i = 0; i < 4; i++) {
            int r = rbase + 32 * i;
            cpa16(stg + 2 * AMAT64 + r * GPITCH + cc * 16, Bf + (size_t)(bn + r) * K + koff);
        }
        CPA_COMMIT();
    };

    float acc[2][4][4];
    #pragma unroll
    for (int mt = 0; mt < 2; mt++)
        #pragma unroll
        for (int nt = 0; nt < 4; nt++)
            #pragma unroll
            for (int q = 0; q < 4; q++) acc[mt][nt][q] = 0.f;

    const uint32_t aOff = (uint32_t)((wm * 32 + (lane & 15)) * GPITCH + (lane >> 4) * 16);
    const uint32_t bOff = (uint32_t)((wn * 32 + (lane & 7) + (lane >> 4) * 8) * GPITCH
                                     + ((lane >> 3) & 1) * 16);

    load_stage(0, 0);

    for (int kt = 0; kt < NK; kt++) {
        const int s = kt & 1;
        asm volatile("cp.async.wait_group 0;" ::: "memory");
        __syncthreads();
        if (kt + 1 < NK) load_stage(s ^ 1, kt + 1);

        const uint32_t stg = sb + s * STG16_64;
        #pragma unroll
        for (int kk = 0; kk < 4; kk++) {
            uint32_t ah[2][4], al[2][4], bf[2][4];
            #pragma unroll
            for (int mt = 0; mt < 2; mt++) {
                ldsm4(ah[mt], stg + aOff + mt * (16 * GPITCH) + kk * 32);
                ldsm4(al[mt], stg + AMAT64 + aOff + mt * (16 * GPITCH) + kk * 32);
            }
            #pragma unroll
            for (int np = 0; np < 2; np++)
                ldsm4(bf[np], stg + 2 * AMAT64 + bOff + np * (16 * GPITCH) + kk * 32);
            #pragma unroll
            for (int mt = 0; mt < 2; mt++)
                #pragma unroll
                for (int nt = 0; nt < 4; nt++)
                    mma_fp16(acc[mt][nt], ah[mt], &bf[nt >> 1][(nt & 1) * 2]);
            #pragma unroll
            for (int mt = 0; mt < 2; mt++)
                #pragma unroll
                for (int nt = 0; nt < 4; nt++)
                    mma_fp16(acc[mt][nt], al[mt], &bf[nt >> 1][(nt & 1) * 2]);
        }
    }

    #pragma unroll
    for (int mt = 0; mt < 2; mt++) {
        const int row0 = bm + wm * 32 + mt * 16 + (lane >> 2);
        #pragma unroll
        for (int nt = 0; nt < 4; nt++) {
            const int col = bn + wn * 32 + nt * 8 + (lane & 3) * 2;
            #pragma unroll
            for (int half = 0; half < 2; half++) {
                const int row = row0 + half * 8;
                const size_t off = (size_t)row * N + col;
                float2 v;
                v.x = acc[mt][nt][half * 2 + 0];
                v.y = acc[mt][nt][half * 2 + 1];
                *(float2*)(Cf + off) = v;
            }
        }
    }
}

// ---------------------------------------------------------------------------
extern "C" void kernel_launch(void* const* d_in, const int* in_sizes, int n_in,
                              void* d_out, int out_size)
{
    const int*   idx     = (const int*)  d_in[0];
    const float* tok_emb = (const float*)d_in[1];
    const float* pos_emb = (const float*)d_in[2];
    const float* ln1_w   = (const float*)d_in[3];
    const float* ln1_b   = (const float*)d_in[4];
    const float* qkv_w   = (const float*)d_in[5];
    const float* out_w   = (const float*)d_in[6];
    const float* ln2_w   = (const float*)d_in[7];
    const float* ln2_b   = (const float*)d_in[8];
    const float* ff1_w   = (const float*)d_in[9];
    const float* ff2_w   = (const float*)d_in[10];
    const float* lnf_w   = (const float*)d_in[11];
    const float* lnf_b   = (const float*)d_in[12];
    float* out = (float*)d_out;

    float *x, *p0, *p1;
    __nv_bfloat16 *h_hi, *h_lo, *y_hi, *y_lo, *ff_hi, *ff_lo;
    __nv_bfloat16 *q_hi, *q_lo, *k_hi, *k_lo, *vt_hi, *vt_lo;
    __nv_bfloat16 *qkvT_hi, *qkvT_lo, *outT_hi, *outT_lo;
    __nv_bfloat16 *ff1T_hi, *ff1T_lo, *ff2T_hi, *ff2T_lo;
    __half *h16_hi, *h16_lo, *emb16;
    cudaGetSymbolAddress((void**)&x,       g_x);
    cudaGetSymbolAddress((void**)&p0,      g_p0);
    cudaGetSymbolAddress((void**)&p1,      g_p1);
    cudaGetSymbolAddress((void**)&h_hi,    g_h_hi);
    cudaGetSymbolAddress((void**)&h_lo,    g_h_lo);
    cudaGetSymbolAddress((void**)&y_hi,    g_y_hi);
    cudaGetSymbolAddress((void**)&y_lo,    g_y_lo);
    cudaGetSymbolAddress((void**)&ff_hi,   g_ff_hi);
    cudaGetSymbolAddress((void**)&ff_lo,   g_ff_lo);
    cudaGetSymbolAddress((void**)&q_hi,    g_q_hi);
    cudaGetSymbolAddress((void**)&q_lo,    g_q_lo);
    cudaGetSymbolAddress((void**)&k_hi,    g_k_hi);
    cudaGetSymbolAddress((void**)&k_lo,    g_k_lo);
    cudaGetSymbolAddress((void**)&vt_hi,   g_vt_hi);
    cudaGetSymbolAddress((void**)&vt_lo,   g_vt_lo);
    cudaGetSymbolAddress((void**)&qkvT_hi, g_qkvT_hi);
    cudaGetSymbolAddress((void**)&qkvT_lo, g_qkvT_lo);
    cudaGetSymbolAddress((void**)&outT_hi, g_outT_hi);
    cudaGetSymbolAddress((void**)&outT_lo, g_outT_lo);
    cudaGetSymbolAddress((void**)&ff1T_hi, g_ff1T_hi);
    cudaGetSymbolAddress((void**)&ff1T_lo, g_ff1T_lo);
    cudaGetSymbolAddress((void**)&ff2T_hi, g_ff2T_hi);
    cudaGetSymbolAddress((void**)&ff2T_lo, g_ff2T_lo);
    cudaGetSymbolAddress((void**)&h16_hi,  g_h16_hi);
    cudaGetSymbolAddress((void**)&h16_lo,  g_h16_lo);
    cudaGetSymbolAddress((void**)&emb16,   g_emb16);

    cudaFuncSetAttribute(flash_hmma3,
                         cudaFuncAttributeMaxDynamicSharedMemorySize, FLASH3_SMEM);
    cudaFuncSetAttribute(gemm_mma64<0>,
                         cudaFuncAttributeMaxDynamicSharedMemorySize, GEMM64_SMEM);
    cudaFuncSetAttribute(gemm_mma64<2>,
                         cudaFuncAttributeMaxDynamicSharedMemorySize, GEMM64_SMEM);
    cudaFuncSetAttribute(gemm_mma64<3>,
                         cudaFuncAttributeMaxDynamicSharedMemorySize, GEMM64_SMEM);
    cudaFuncSetAttribute(gemm_f16_64,
                         cudaFuncAttributeMaxDynamicSharedMemorySize, GEMM16_SMEM);

    // ---- weight prep (batched over layers) ----
    wprep_S16<<<8192, 256>>>((const float4*)tok_emb, emb16, VV * DD / 4);
    wprep_T<<<dim3(3*DD/32, DD/32, LL), 256>>>(qkv_w, qkvT_hi, qkvT_lo, DD, 3*DD);
    wprep_T<<<dim3(DD/32,   DD/32, LL), 256>>>(out_w, outT_hi, outT_lo, DD, DD);
    wprep_T<<<dim3(4*DD/32, DD/32, LL), 256>>>(ff1_w, ff1T_hi, ff1T_lo, DD, 4*DD);
    wprep_T<<<dim3(DD/32, 4*DD/32, LL), 256>>>(ff2_w, ff2T_hi, ff2T_lo, 4*DD, DD);

    embed_kernel<<<MM, 256>>>(idx, tok_emb, pos_emb, x);

    for (int l = 0; l < LL; l++) {
        // ln1: fused add of previous layer's ff2 partials (none for layer 0)
        ln_kernel<0><<<MM, 256>>>(x, (l == 0) ? nullptr : p0, p1,
                                  ln1_w + l*DD, ln1_b + l*DD, h_hi, h_lo, x);
        gemm_mma64<3><<<dim3(3*DD/128, MM/64), 256, GEMM64_SMEM>>>(
            h_hi, h_lo, qkvT_hi + (size_t)l*3*DD*DD, qkvT_lo + (size_t)l*3*DD*DD,
            nullptr, nullptr, nullptr, nullptr,
            q_hi, q_lo, k_hi, k_lo, vt_hi, vt_lo, MM, 3*DD, DD, DD);
        flash_hmma3<<<dim3(TT/128, HH, BB), 256, FLASH3_SMEM>>>(
            q_hi, q_lo, k_hi, k_lo, vt_hi, vt_lo, y_hi, y_lo);
        // out-proj: split-K=2 into partials
        gemm_mma64<0><<<dim3(DD/128, 2*MM/64), 256, GEMM64_SMEM>>>(
            y_hi, y_lo, outT_hi + (size_t)l*DD*DD, outT_lo + (size_t)l*DD*DD,
            p0, p1, nullptr, nullptr,
            nullptr, nullptr, nullptr, nullptr, nullptr, nullptr,
            MM, DD, DD, DD/2);
        // ln2: fused x += p0+p1
        ln_kernel<0><<<MM, 256>>>(x, p0, p1,
                                  ln2_w + l*DD, ln2_b + l*DD, h_hi, h_lo, x);
        gemm_mma64<2><<<dim3(4*DD/128, MM/64), 256, GEMM64_SMEM>>>(
            h_hi, h_lo, ff1T_hi + (size_t)l*4*DD*DD, ff1T_lo + (size_t)l*4*DD*DD,
            nullptr, nullptr, ff_hi, ff_lo,
            nullptr, nullptr, nullptr, nullptr, nullptr, nullptr,
            MM, 4*DD, DD, DD);
        // ff2: split-K=2 into partials (folded into next ln1 / lnf)
        gemm_mma64<0><<<dim3(DD/128, 2*MM/64), 256, GEMM64_SMEM>>>(
            ff_hi, ff_lo, ff2T_hi + (size_t)l*4*DD*DD, ff2T_lo + (size_t)l*4*DD*DD,
            p0, p1, nullptr, nullptr,
            nullptr, nullptr, nullptr, nullptr, nullptr, nullptr,
            MM, DD, 4*DD, 2*DD);
    }

    // lnf: fused x += p0+p1 from the last ff2 (no xout write needed)
    ln_kernel<1><<<MM, 256>>>(x, p0, p1, lnf_w, lnf_b, h16_hi, h16_lo, nullptr);
    gemm_f16_64<<<dim3(VV/128, MM/64), 256, GEMM16_SMEM>>>(
        h16_hi, h16_lo, emb16, out, MM, VV, DD, 25);
}